// round 4
// baseline (speedup 1.0000x reference)
#include <cuda_runtime.h>
#include <cub/cub.cuh>
#include <math.h>

#define NB 8
#define CI 256
#define HH 100
#define WW 100
#define KA 9
#define PP 90000          // anchors per image
#define PRE 3000
#define POST 300
#define NW 94             // 32-bit words to cover PRE bits

#define OFF_CLS  0
#define OFF_REG  1440000
#define OFF_ROIS 4320000
#define OFF_INDS 4329600
#define OFF_ANCH 4332000

// ---------------- scratch (static device memory; no runtime allocation) -------------
__device__ double g_h[NB*CI*HH*WW];          // conv3x3+relu output, f64 (164 MB)
__device__ double g_w1t[CI*9*CI];            // w1 transposed to [ic][k][oc], f64
__device__ double g_score[NB*PP];
__device__ double g_reg[NB*PP*4];            // f64 reg head output (feeds decode)
__device__ double g_boxes[NB*PP*4];
__device__ unsigned long long g_ki[NB*PP], g_ko[NB*PP];
__device__ unsigned g_vi[NB*PP], g_vo[NB*PP];
__device__ int g_segoff[9] = {0,90000,180000,270000,360000,450000,540000,630000,720000};
__device__ double g_bsort[NB*PRE*4];
__device__ double g_area[NB*PRE];
__device__ int   g_valid[NB*PRE];
__device__ unsigned g_mask[NB*PRE*NW];
__device__ unsigned char g_cubtmp[48u<<20];

// ---------------- anchor base (double math, rounded to f32 = np.float32 array) ------
__device__ __forceinline__ void anchor_ab(int k, float& a0, float& a1, float& a2, float& a3) {
    int ri = k / 3, si = k % 3;
    double r = (ri == 0) ? 0.5 : ((ri == 1) ? 1.0 : 2.0);
    double s = (si == 0) ? 8.0 : ((si == 1) ? 16.0 : 32.0);
    double h = 16.0 * s * sqrt(r);
    double w = 16.0 * s * sqrt(1.0 / r);
    a0 = (float)(8.0 - h / 2.0);
    a1 = (float)(8.0 - w / 2.0);
    a2 = (float)(8.0 + h / 2.0);
    a3 = (float)(8.0 + w / 2.0);
}

// ---------------- weight transpose for conv3x3: [oc][ic][k] -> [ic][k][oc], f64 ------
__global__ void wtrans(const float* __restrict__ w1) {
    int idx = blockIdx.x * 256 + threadIdx.x;
    if (idx >= CI * 9 * CI) return;
    int oc = idx % CI;
    int t  = idx / CI;
    int kk = t % 9;
    int ic = t / 9;
    g_w1t[idx] = (double)w1[(oc * CI + ic) * 9 + kk];
}

// ---------------- conv 3x3, pad 1, 256->256, +bias, ReLU, all f64 --------------------
// block: 256 threads, computes 8 rows x 16 cols x 64 oc
__global__ __launch_bounds__(256, 2) void conv3(const float* __restrict__ x,
                                                const float* __restrict__ b1) {
    __shared__ double sx[8][10][18];
    __shared__ double sw[8][9][64];
    int n   = blockIdx.z >> 2;
    int ocb = (blockIdx.z & 3) * 64;
    int bx0 = blockIdx.x * 16;
    int by0 = blockIdx.y * 8;
    int tid = threadIdx.x;
    int c   = tid & 15;       // column within tile
    int ocg = tid >> 4;       // 0..15, 4 oc each

    double acc[8][4];
    #pragma unroll
    for (int r = 0; r < 8; r++)
        #pragma unroll
        for (int j = 0; j < 4; j++) acc[r][j] = 0.0;

    for (int icb = 0; icb < CI; icb += 8) {
        for (int idx = tid; idx < 8 * 10 * 18; idx += 256) {
            int ic = idx / 180, rem = idx % 180;
            int r = rem / 18, cc = rem % 18;
            int gy = by0 + r - 1, gx = bx0 + cc - 1;
            float v = 0.f;
            if ((unsigned)gy < 100u && (unsigned)gx < 100u)
                v = x[((n * CI + icb + ic) * HH + gy) * WW + gx];
            sx[ic][r][cc] = (double)v;
        }
        for (int idx = tid; idx < 8 * 9 * 64; idx += 256) {
            int ic = idx / 576, rem = idx % 576;
            int kk = rem / 64, oc = rem & 63;
            sw[ic][kk][oc] = g_w1t[((icb + ic) * 9 + kk) * CI + ocb + oc];
        }
        __syncthreads();

        #pragma unroll
        for (int ic = 0; ic < 8; ic++) {
            #pragma unroll
            for (int ky = 0; ky < 3; ky++) {
                #pragma unroll
                for (int kx = 0; kx < 3; kx++) {
                    double w0 = sw[ic][ky * 3 + kx][ocg * 4 + 0];
                    double w1v = sw[ic][ky * 3 + kx][ocg * 4 + 1];
                    double w2 = sw[ic][ky * 3 + kx][ocg * 4 + 2];
                    double w3 = sw[ic][ky * 3 + kx][ocg * 4 + 3];
                    #pragma unroll
                    for (int r = 0; r < 8; r++) {
                        double xv = sx[ic][r + ky][c + kx];
                        acc[r][0] = fma(xv, w0, acc[r][0]);
                        acc[r][1] = fma(xv, w1v, acc[r][1]);
                        acc[r][2] = fma(xv, w2, acc[r][2]);
                        acc[r][3] = fma(xv, w3, acc[r][3]);
                    }
                }
            }
        }
        __syncthreads();
    }

    #pragma unroll
    for (int j = 0; j < 4; j++) {
        int oc = ocb + ocg * 4 + j;
        double b = (double)b1[oc];
        #pragma unroll
        for (int r = 0; r < 8; r++) {
            int gy = by0 + r, gx = bx0 + c;
            if (gy < HH && gx < WW)
                g_h[((n * CI + oc) * HH + gy) * WW + gx] = fmax(acc[r][j] + b, 0.0);
        }
    }
}

// ---------------- cls 1x1 head (18ch), f64: writes f32 cls out + f64 scores ----------
__global__ __launch_bounds__(128) void cls_head(const float* __restrict__ wc,
                                                const float* __restrict__ bc,
                                                float* __restrict__ out) {
    __shared__ double sw1[64][18];
    int n = blockIdx.y;
    int p = blockIdx.x * 128 + threadIdx.x;   // pixel id

    double acc[18];
    #pragma unroll
    for (int o = 0; o < 18; o++) acc[o] = 0.0;

    for (int icb = 0; icb < CI; icb += 64) {
        for (int idx = threadIdx.x; idx < 64 * 18; idx += 128) {
            int ic = idx / 18, oc = idx % 18;
            sw1[ic][oc] = (double)wc[oc * CI + icb + ic];
        }
        __syncthreads();
        if (p < HH * WW) {
            for (int ic = 0; ic < 64; ic++) {
                double hv = g_h[(n * CI + icb + ic) * (HH * WW) + p];
                #pragma unroll
                for (int oc = 0; oc < 18; oc++) acc[oc] = fma(hv, sw1[ic][oc], acc[oc]);
            }
        }
        __syncthreads();
    }
    if (p >= HH * WW) return;

    double l[18];
    #pragma unroll
    for (int c18 = 0; c18 < 18; c18++) {
        l[c18] = acc[c18] + (double)bc[c18];
        int k = c18 >> 1, cc = c18 & 1;
        out[OFF_CLS + (n * 2 + cc) * PP + p * KA + k] = (float)l[c18];
    }
    #pragma unroll
    for (int k = 0; k < KA; k++) {
        double s = 1.0 / (1.0 + exp(l[2 * k] - l[2 * k + 1]));
        g_score[n * PP + p * KA + k] = s;
    }
}

// ---------------- reg 1x1 head (36ch), f64: writes f32 reg out + f64 g_reg -----------
__global__ __launch_bounds__(128) void reg_head(const float* __restrict__ wr,
                                                const float* __restrict__ br,
                                                float* __restrict__ out) {
    __shared__ double sw1[64][36];
    int n = blockIdx.y;
    int p = blockIdx.x * 128 + threadIdx.x;

    double acc[36];
    #pragma unroll
    for (int o = 0; o < 36; o++) acc[o] = 0.0;

    for (int icb = 0; icb < CI; icb += 64) {
        for (int idx = threadIdx.x; idx < 64 * 36; idx += 128) {
            int ic = idx / 36, oc = idx % 36;
            sw1[ic][oc] = (double)wr[oc * CI + icb + ic];
        }
        __syncthreads();
        if (p < HH * WW) {
            for (int ic = 0; ic < 64; ic++) {
                double hv = g_h[(n * CI + icb + ic) * (HH * WW) + p];
                #pragma unroll
                for (int oc = 0; oc < 36; oc++) acc[oc] = fma(hv, sw1[ic][oc], acc[oc]);
            }
        }
        __syncthreads();
    }
    if (p >= HH * WW) return;

    #pragma unroll
    for (int c36 = 0; c36 < 36; c36++) {
        int k = c36 >> 2, j = c36 & 3;
        double v = acc[c36] + (double)br[c36];
        out[OFF_REG + n * (PP * 4) + (p * KA + k) * 4 + j] = (float)v;
        g_reg[(size_t)n * (PP * 4) + (p * KA + k) * 4 + j] = v;
    }
}

// ---------------- decode all anchors, clip, min-size, build f64-bit sort keys --------
__global__ void decode_all(const int* __restrict__ pimw,
                           const int* __restrict__ pimh) {
    int idx = blockIdx.x * 256 + threadIdx.x;
    if (idx >= NB * PP) return;
    int n = idx / PP, i = idx - n * PP;
    int cell = i / KA, k = i - cell * KA;
    int y = cell / WW, x = cell - y * WW;

    // anchors are f32 in the reference (np.float32); replicate f32 arithmetic,
    // then promote to f64 exactly as JAX type promotion does.
    float a0, a1, a2, a3;
    anchor_ab(k, a0, a1, a2, a3);
    float sy = (float)(y * 16), sx0 = (float)(x * 16);
    float af0 = sy + a0, af1 = sx0 + a1, af2 = sy + a2, af3 = sx0 + a3;
    float ahf = af2 - af0, awf = af3 - af1;
    float ayf = af0 + 0.5f * ahf, axf = af1 + 0.5f * awf;
    double ah = (double)ahf, aw = (double)awf, ay = (double)ayf, ax = (double)axf;

    const double* lp = &g_reg[(size_t)n * (PP * 4) + (size_t)i * 4];
    double dy = lp[0], dx = lp[1], dh = lp[2], dw = lp[3];
    double cy = dy * ah + ay, cx = dx * aw + ax;
    double hb = exp(dh) * ah, wb = exp(dw) * aw;

    int wv = pimw[0], hv = pimh[0];
    double imw = (wv > 65536 || wv < 0) ? (double)__int_as_float(wv) : (double)wv;
    double imh = (hv > 65536 || hv < 0) ? (double)__int_as_float(hv) : (double)hv;

    double y1 = fmin(fmax(cy - 0.5 * hb, 0.0), imh);
    double y2 = fmin(fmax(cy + 0.5 * hb, 0.0), imh);
    double x1 = fmin(fmax(cx - 0.5 * wb, 0.0), imw);
    double x2 = fmin(fmax(cx + 0.5 * wb, 0.0), imw);
    bool big = (y2 - y1 >= 16.0) && (x2 - x1 >= 16.0);

    double* bp = &g_boxes[(size_t)idx * 4];
    bp[0] = y1; bp[1] = x1; bp[2] = y2; bp[3] = x2;

    // scores are strictly in (0,1): positive double bits are order-preserving, nonzero
    g_ki[idx] = big ? __double_as_longlong(g_score[idx]) : 0ull;
    g_vi[idx] = (unsigned)i;
}

// ---------------- gather top PRE per batch ------------------------------------------
__global__ void gather_top() {
    int idx = blockIdx.x * 256 + threadIdx.x;
    if (idx >= NB * PRE) return;
    int n = idx / PRE, r = idx - n * PRE;
    unsigned long long key = g_ko[n * PP + r];
    unsigned i = g_vo[n * PP + r];
    const double* bp = &g_boxes[((size_t)n * PP + i) * 4];
    double y1 = bp[0], x1 = bp[1], y2 = bp[2], x2 = bp[3];
    double* d = &g_bsort[(size_t)idx * 4];
    d[0] = y1; d[1] = x1; d[2] = y2; d[3] = x2;
    g_area[idx]  = (y2 - y1) * (x2 - x1);
    g_valid[idx] = (key != 0ull) ? 1 : 0;
}

// ---------------- NMS suppression mask, f64 IoU (bits j>i only, words w >= i/32) -----
__global__ __launch_bounds__(96) void nms_mask() {
    int i = blockIdx.x, n = blockIdx.y;
    const double* bi = &g_bsort[((size_t)n * PRE + i) * 4];
    double y1 = bi[0], x1 = bi[1], y2 = bi[2], x2 = bi[3];
    double ai = g_area[n * PRE + i];
    int lane = threadIdx.x & 31, wp = threadIdx.x >> 5;
    int wstart = i >> 5;
    for (int w = wstart + wp; w < NW; w += 3) {
        int j = w * 32 + lane;
        bool bit = false;
        if (j < PRE && j > i) {
            const double* bj = &g_bsort[((size_t)n * PRE + j) * 4];
            double yy1 = fmax(y1, bj[0]);
            double xx1 = fmax(x1, bj[1]);
            double yy2 = fmin(y2, bj[2]);
            double xx2 = fmin(x2, bj[3]);
            double inter = fmax(yy2 - yy1, 0.0) * fmax(xx2 - xx1, 0.0);
            double iou = inter / (ai + g_area[n * PRE + j] - inter + 1e-9);
            bit = iou > 0.7;
        }
        unsigned m = __ballot_sync(0xffffffffu, bit);
        if (lane == 0) g_mask[((size_t)n * PRE + i) * NW + w] = m;
    }
}

// ---------------- serial greedy scan, 1 warp per batch, write rois + inds ------------
__global__ __launch_bounds__(32) void nms_scan(float* __restrict__ out) {
    int n = blockIdx.x;
    int lane = threadIdx.x;
    unsigned rm0 = 0, rm1 = 0, rm2 = 0;   // lane holds words lane, lane+32, lane+64
    int count = 0;
    for (int i = 0; i < PRE && count < POST; i++) {
        int wi = i >> 5;
        int slot = wi >> 5;
        int src  = wi & 31;
        unsigned myw = (slot == 0) ? rm0 : ((slot == 1) ? rm1 : rm2);
        unsigned word = __shfl_sync(0xffffffffu, myw, src);
        bool kept = g_valid[n * PRE + i] && !((word >> (i & 31)) & 1u);
        if (kept) {
            if (lane < 4)
                out[OFF_ROIS + (n * POST + count) * 4 + lane] =
                    (float)g_bsort[((size_t)n * PRE + i) * 4 + lane];
            count++;
            const unsigned* mrow = &g_mask[((size_t)n * PRE + i) * NW];
            int w0 = lane;
            int w1 = lane + 32;
            int w2 = lane + 64;
            if (w0 >= wi && w0 < NW) rm0 |= mrow[w0];
            if (w1 >= wi && w1 < NW) rm1 |= mrow[w1];
            if (w2 >= wi && w2 < NW) rm2 |= mrow[w2];
        }
    }
    for (int m = count; m < POST; m++)
        if (lane < 4) out[OFF_ROIS + (n * POST + m) * 4 + lane] = 0.f;
    for (int m = lane; m < POST; m += 32)
        out[OFF_INDS + n * POST + m] = (float)n;
}

// ---------------- anchors output (f32, replicating numpy f32 arithmetic) -------------
__global__ void anchors_k(float* __restrict__ out) {
    int i = blockIdx.x * 256 + threadIdx.x;
    if (i >= PP) return;
    int cell = i / KA, k = i - cell * KA;
    int y = cell / WW, x = cell - y * WW;
    float a0, a1, a2, a3;
    anchor_ab(k, a0, a1, a2, a3);
    float sy = (float)(y * 16), sx = (float)(x * 16);
    out[OFF_ANCH + i * 4 + 0] = sy + a0;
    out[OFF_ANCH + i * 4 + 1] = sx + a1;
    out[OFF_ANCH + i * 4 + 2] = sy + a2;
    out[OFF_ANCH + i * 4 + 3] = sx + a3;
}

// ---------------- launch -------------------------------------------------------------
extern "C" void kernel_launch(void* const* d_in, const int* in_sizes, int n_in,
                              void* d_out, int out_size) {
    const float* x  = (const float*)d_in[0];
    const float* w1 = (const float*)d_in[1];
    const float* b1 = (const float*)d_in[2];
    const float* wc = (const float*)d_in[3];
    const float* bc = (const float*)d_in[4];
    const float* wr = (const float*)d_in[5];
    const float* br = (const float*)d_in[6];
    const int* imw  = (const int*)d_in[7];
    const int* imh  = (const int*)d_in[8];
    float* out = (float*)d_out;

    wtrans<<<(CI * 9 * CI + 255) / 256, 256>>>(w1);
    conv3<<<dim3(7, 13, NB * 4), 256>>>(x, b1);
    cls_head<<<dim3(79, NB), 128>>>(wc, bc, out);
    reg_head<<<dim3(79, NB), 128>>>(wr, br, out);
    decode_all<<<(NB * PP + 255) / 256, 256>>>(imw, imh);

    void *pt, *pki, *pko, *pvi, *pvo, *poff;
    cudaGetSymbolAddress(&pt,  g_cubtmp);
    cudaGetSymbolAddress(&pki, g_ki);
    cudaGetSymbolAddress(&pko, g_ko);
    cudaGetSymbolAddress(&pvi, g_vi);
    cudaGetSymbolAddress(&pvo, g_vo);
    cudaGetSymbolAddress(&poff, g_segoff);
    size_t tb = sizeof(g_cubtmp);
    cub::DeviceSegmentedRadixSort::SortPairsDescending(
        pt, tb,
        (const unsigned long long*)pki, (unsigned long long*)pko,
        (const unsigned*)pvi, (unsigned*)pvo,
        NB * PP, NB,
        (const int*)poff, (const int*)poff + 1,
        0, 64, (cudaStream_t)0);

    gather_top<<<(NB * PRE + 255) / 256, 256>>>();
    nms_mask<<<dim3(PRE, NB), 96>>>();
    nms_scan<<<NB, 32>>>(out);
    anchors_k<<<(PP + 255) / 256, 256>>>(out);
}

// round 5
// speedup vs baseline: 6.9092x; 6.9092x over previous
#include <cuda_runtime.h>
#include <cub/cub.cuh>
#include <math.h>

#define NB 8
#define CI 256
#define HH 100
#define WW 100
#define KA 9
#define PP 90000          // anchors per image
#define PRE 3000
#define POST 300
#define NW 94             // 32-bit words to cover PRE bits

#define OFF_CLS  0
#define OFF_REG  1440000
#define OFF_ROIS 4320000
#define OFF_INDS 4329600
#define OFF_ANCH 4332000

// ---------------- scratch (static device memory; no runtime allocation) -------------
__device__ float  g_hhi[NB*CI*HH*WW];        // conv output hi part (82 MB)
__device__ float  g_hlo[NB*CI*HH*WW];        // conv output lo part (82 MB)
__device__ float  g_w1tf[CI*9*CI];           // w1 transposed to [ic][k][oc], f32
__device__ double g_score[NB*PP];
__device__ double g_reg[NB*PP*4];            // f64 reg head output (feeds decode)
__device__ double g_boxes[NB*PP*4];
__device__ unsigned long long g_ki[NB*PP], g_ko[NB*PP];
__device__ unsigned g_vi[NB*PP], g_vo[NB*PP];
__device__ int g_segoff[9] = {0,90000,180000,270000,360000,450000,540000,630000,720000};
__device__ double g_bsort[NB*PRE*4];
__device__ double g_area[NB*PRE];
__device__ float4 g_bsf[NB*PRE];             // f32 mirror of boxes for fast IoU
__device__ float  g_areaf[NB*PRE];
__device__ int   g_valid[NB*PRE];
__device__ unsigned g_mask[NB*PRE*NW];
__device__ unsigned char g_cubtmp[48u<<20];

// ---- df32 compensated MAC: exact product (Dekker) + biased Fast2Sum accumulation ----
// Requires |H| >= |p| at all times (guaranteed by bias seed). All ops non-contractable.
#define MAC(H, L, a, b) {                         \
    float p  = __fmul_rn((a), (b));               \
    float pe = __fmaf_rn((a), (b), -p);           \
    float t  = __fadd_rn((H), p);                 \
    float z  = __fsub_rn(t, (H));                 \
    float e  = __fsub_rn(p, z);                   \
    (H) = t;                                      \
    (L) = __fadd_rn((L), __fadd_rn(e, pe));       \
}

// ---------------- anchor base (double math, rounded to f32 = np.float32 array) ------
__device__ __forceinline__ void anchor_ab(int k, float& a0, float& a1, float& a2, float& a3) {
    int ri = k / 3, si = k % 3;
    double r = (ri == 0) ? 0.5 : ((ri == 1) ? 1.0 : 2.0);
    double s = (si == 0) ? 8.0 : ((si == 1) ? 16.0 : 32.0);
    double h = 16.0 * s * sqrt(r);
    double w = 16.0 * s * sqrt(1.0 / r);
    a0 = (float)(8.0 - h / 2.0);
    a1 = (float)(8.0 - w / 2.0);
    a2 = (float)(8.0 + h / 2.0);
    a3 = (float)(8.0 + w / 2.0);
}

// ---------------- weight transpose for conv3x3: [oc][ic][k] -> [ic][k][oc] -----------
__global__ void wtrans(const float* __restrict__ w1) {
    int idx = blockIdx.x * 256 + threadIdx.x;
    if (idx >= CI * 9 * CI) return;
    int oc = idx % CI;
    int t  = idx / CI;
    int kk = t % 9;
    int ic = t / 9;
    g_w1tf[idx] = w1[(oc * CI + ic) * 9 + kk];
}

// ---------------- conv 3x3, pad 1, 256->256, +bias, ReLU, df32 compensated -----------
// block: 256 threads; tile: 4 rows x 16 cols x 64 oc; thread: 4 rows x 4 oc
__global__ __launch_bounds__(256) void conv3(const float* __restrict__ x,
                                             const float* __restrict__ b1) {
    __shared__ float sx[8][6][18];
    __shared__ float sw[8][9][64];
    int n   = blockIdx.z >> 2;
    int ocb = (blockIdx.z & 3) * 64;
    int bx0 = blockIdx.x * 16;
    int by0 = blockIdx.y * 4;
    int tid = threadIdx.x;
    int c   = tid & 15;       // column within tile
    int g   = tid >> 4;       // 0..15, 4 oc each

    const float BIAS = 64.0f;
    float hi[4][4], lo[4][4];
    #pragma unroll
    for (int r = 0; r < 4; r++)
        #pragma unroll
        for (int j = 0; j < 4; j++) { hi[r][j] = BIAS; lo[r][j] = 0.f; }

    for (int icb = 0; icb < CI; icb += 8) {
        for (int idx = tid; idx < 8 * 6 * 18; idx += 256) {
            int ic = idx / 108, rem = idx % 108;
            int r = rem / 18, cc = rem % 18;
            int gy = by0 + r - 1, gx = bx0 + cc - 1;
            float v = 0.f;
            if ((unsigned)gy < 100u && (unsigned)gx < 100u)
                v = x[((n * CI + icb + ic) * HH + gy) * WW + gx];
            sx[ic][r][cc] = v;
        }
        for (int idx = tid; idx < 8 * 9 * 64; idx += 256) {
            int ic = idx / 576, rem = idx % 576;
            int kk = rem / 64, oc = rem & 63;
            sw[ic][kk][oc] = g_w1tf[((icb + ic) * 9 + kk) * CI + ocb + oc];
        }
        __syncthreads();

        #pragma unroll 2
        for (int ic = 0; ic < 8; ic++) {
            #pragma unroll
            for (int ky = 0; ky < 3; ky++) {
                #pragma unroll
                for (int kx = 0; kx < 3; kx++) {
                    float4 wv = *(const float4*)&sw[ic][ky * 3 + kx][g * 4];
                    #pragma unroll
                    for (int r = 0; r < 4; r++) {
                        float xv = sx[ic][r + ky][c + kx];
                        MAC(hi[r][0], lo[r][0], xv, wv.x);
                        MAC(hi[r][1], lo[r][1], xv, wv.y);
                        MAC(hi[r][2], lo[r][2], xv, wv.z);
                        MAC(hi[r][3], lo[r][3], xv, wv.w);
                    }
                }
            }
        }
        __syncthreads();
    }

    #pragma unroll
    for (int j = 0; j < 4; j++) {
        int oc = ocb + g * 4 + j;
        double b = (double)b1[oc];
        #pragma unroll
        for (int r = 0; r < 4; r++) {
            int gy = by0 + r, gx = bx0 + c;
            if (gy < HH && gx < WW) {
                double v = (double)__fsub_rn(hi[r][j], BIAS) + (double)lo[r][j] + b;
                v = fmax(v, 0.0);
                float vh = (float)v;
                float vl = (float)(v - (double)vh);
                size_t o = ((size_t)(n * CI + oc) * HH + gy) * WW + gx;
                g_hhi[o] = vh;
                g_hlo[o] = vl;
            }
        }
    }
}

// ---------------- fused 1x1 heads (18 cls + 36 reg), df32 compensated ----------------
__global__ __launch_bounds__(128) void heads(const float* __restrict__ wc,
                                             const float* __restrict__ bc,
                                             const float* __restrict__ wr,
                                             const float* __restrict__ br,
                                             float* __restrict__ out) {
    __shared__ float sw1[64][54];
    int n = blockIdx.y;
    int p = blockIdx.x * 128 + threadIdx.x;   // pixel id

    const float BIAS = 16.0f;
    float Hi[54], Lo[54];
    #pragma unroll
    for (int o = 0; o < 54; o++) { Hi[o] = BIAS; Lo[o] = 0.f; }

    for (int icb = 0; icb < CI; icb += 64) {
        for (int idx = threadIdx.x; idx < 64 * 54; idx += 128) {
            int ic = idx / 54, oc = idx % 54;
            sw1[ic][oc] = (oc < 18) ? wc[oc * CI + icb + ic]
                                    : wr[(oc - 18) * CI + icb + ic];
        }
        __syncthreads();
        if (p < HH * WW) {
            #pragma unroll 4
            for (int ic = 0; ic < 64; ic++) {
                size_t o = (size_t)(n * CI + icb + ic) * (HH * WW) + p;
                float hh = g_hhi[o];
                float hl = g_hlo[o];
                #pragma unroll
                for (int oc = 0; oc < 54; oc++) {
                    float w = sw1[ic][oc];
                    float q = __fmul_rn(hl, w);   // lo-part product (err negligible)
                    MAC(Hi[oc], Lo[oc], hh, w);
                    Lo[oc] = __fadd_rn(Lo[oc], q);
                }
            }
        }
        __syncthreads();
    }
    if (p >= HH * WW) return;

    double l[18];
    #pragma unroll
    for (int c18 = 0; c18 < 18; c18++) {
        l[c18] = (double)__fsub_rn(Hi[c18], BIAS) + (double)Lo[c18] + (double)bc[c18];
        int k = c18 >> 1, cc = c18 & 1;
        out[OFF_CLS + (n * 2 + cc) * PP + p * KA + k] = (float)l[c18];
    }
    #pragma unroll
    for (int k = 0; k < KA; k++) {
        double s = 1.0 / (1.0 + exp(l[2 * k] - l[2 * k + 1]));
        g_score[n * PP + p * KA + k] = s;
    }
    #pragma unroll
    for (int c36 = 0; c36 < 36; c36++) {
        int k = c36 >> 2, j = c36 & 3;
        double v = (double)__fsub_rn(Hi[18 + c36], BIAS) + (double)Lo[18 + c36]
                 + (double)br[c36];
        out[OFF_REG + n * (PP * 4) + (p * KA + k) * 4 + j] = (float)v;
        g_reg[(size_t)n * (PP * 4) + (p * KA + k) * 4 + j] = v;
    }
}

// ---------------- decode all anchors, clip, min-size, build f64-bit sort keys --------
__global__ void decode_all(const int* __restrict__ pimw,
                           const int* __restrict__ pimh) {
    int idx = blockIdx.x * 256 + threadIdx.x;
    if (idx >= NB * PP) return;
    int n = idx / PP, i = idx - n * PP;
    int cell = i / KA, k = i - cell * KA;
    int y = cell / WW, x = cell - y * WW;

    float a0, a1, a2, a3;
    anchor_ab(k, a0, a1, a2, a3);
    float sy = (float)(y * 16), sx0 = (float)(x * 16);
    float af0 = sy + a0, af1 = sx0 + a1, af2 = sy + a2, af3 = sx0 + a3;
    float ahf = af2 - af0, awf = af3 - af1;
    float ayf = af0 + 0.5f * ahf, axf = af1 + 0.5f * awf;
    double ah = (double)ahf, aw = (double)awf, ay = (double)ayf, ax = (double)axf;

    const double* lp = &g_reg[(size_t)n * (PP * 4) + (size_t)i * 4];
    double dy = lp[0], dx = lp[1], dh = lp[2], dw = lp[3];
    double cy = dy * ah + ay, cx = dx * aw + ax;
    double hb = exp(dh) * ah, wb = exp(dw) * aw;

    int wv = pimw[0], hv = pimh[0];
    double imw = (wv > 65536 || wv < 0) ? (double)__int_as_float(wv) : (double)wv;
    double imh = (hv > 65536 || hv < 0) ? (double)__int_as_float(hv) : (double)hv;

    double y1 = fmin(fmax(cy - 0.5 * hb, 0.0), imh);
    double y2 = fmin(fmax(cy + 0.5 * hb, 0.0), imh);
    double x1 = fmin(fmax(cx - 0.5 * wb, 0.0), imw);
    double x2 = fmin(fmax(cx + 0.5 * wb, 0.0), imw);
    bool big = (y2 - y1 >= 16.0) && (x2 - x1 >= 16.0);

    double* bp = &g_boxes[(size_t)idx * 4];
    bp[0] = y1; bp[1] = x1; bp[2] = y2; bp[3] = x2;

    g_ki[idx] = big ? __double_as_longlong(g_score[idx]) : 0ull;
    g_vi[idx] = (unsigned)i;
}

// ---------------- gather top PRE per batch ------------------------------------------
__global__ void gather_top() {
    int idx = blockIdx.x * 256 + threadIdx.x;
    if (idx >= NB * PRE) return;
    int n = idx / PRE, r = idx - n * PRE;
    unsigned long long key = g_ko[n * PP + r];
    unsigned i = g_vo[n * PP + r];
    const double* bp = &g_boxes[((size_t)n * PP + i) * 4];
    double y1 = bp[0], x1 = bp[1], y2 = bp[2], x2 = bp[3];
    double* d = &g_bsort[(size_t)idx * 4];
    d[0] = y1; d[1] = x1; d[2] = y2; d[3] = x2;
    double a = (y2 - y1) * (x2 - x1);
    g_area[idx]  = a;
    g_bsf[idx]   = make_float4((float)y1, (float)x1, (float)y2, (float)x2);
    g_areaf[idx] = (float)a;
    g_valid[idx] = (key != 0ull) ? 1 : 0;
}

// ------- NMS mask: f32 IoU with f64 fallback in a guard band around the threshold ----
__global__ __launch_bounds__(96) void nms_mask() {
    int i = blockIdx.x, n = blockIdx.y;
    float4 bi = g_bsf[n * PRE + i];
    float ai = g_areaf[n * PRE + i];
    int lane = threadIdx.x & 31, wp = threadIdx.x >> 5;
    int wstart = i >> 5;
    for (int w = wstart + wp; w < NW; w += 3) {
        int j = w * 32 + lane;
        bool bit = false;
        if (j < PRE && j > i) {
            float4 bj = g_bsf[n * PRE + j];
            float yy1 = fmaxf(bi.x, bj.x);
            float xx1 = fmaxf(bi.y, bj.y);
            float yy2 = fminf(bi.z, bj.z);
            float xx2 = fminf(bi.w, bj.w);
            float inter = fmaxf(yy2 - yy1, 0.f) * fmaxf(xx2 - xx1, 0.f);
            float iou = inter / (ai + g_areaf[n * PRE + j] - inter + 1e-9f);
            if (fabsf(iou - 0.7f) < 1e-4f) {
                // near-threshold: recompute the decision in f64 exactly
                const double* di = &g_bsort[((size_t)n * PRE + i) * 4];
                const double* dj = &g_bsort[((size_t)n * PRE + j) * 4];
                double dy1 = fmax(di[0], dj[0]);
                double dx1 = fmax(di[1], dj[1]);
                double dy2 = fmin(di[2], dj[2]);
                double dx2 = fmin(di[3], dj[3]);
                double dint = fmax(dy2 - dy1, 0.0) * fmax(dx2 - dx1, 0.0);
                double diou = dint / (g_area[n * PRE + i] + g_area[n * PRE + j]
                                      - dint + 1e-9);
                bit = diou > 0.7;
            } else {
                bit = iou > 0.7f;
            }
        }
        unsigned m = __ballot_sync(0xffffffffu, bit);
        if (lane == 0) g_mask[((size_t)n * PRE + i) * NW + w] = m;
    }
}

// ---------------- serial greedy scan, 1 warp per batch, write rois + inds ------------
__global__ __launch_bounds__(32) void nms_scan(float* __restrict__ out) {
    int n = blockIdx.x;
    int lane = threadIdx.x;
    unsigned rm0 = 0, rm1 = 0, rm2 = 0;   // lane holds words lane, lane+32, lane+64
    int count = 0;
    for (int i = 0; i < PRE && count < POST; i++) {
        int wi = i >> 5;
        int slot = wi >> 5;
        int src  = wi & 31;
        unsigned myw = (slot == 0) ? rm0 : ((slot == 1) ? rm1 : rm2);
        unsigned word = __shfl_sync(0xffffffffu, myw, src);
        bool kept = g_valid[n * PRE + i] && !((word >> (i & 31)) & 1u);
        if (kept) {
            if (lane < 4)
                out[OFF_ROIS + (n * POST + count) * 4 + lane] =
                    (float)g_bsort[((size_t)n * PRE + i) * 4 + lane];
            count++;
            const unsigned* mrow = &g_mask[((size_t)n * PRE + i) * NW];
            int w0 = lane;
            int w1 = lane + 32;
            int w2 = lane + 64;
            if (w0 >= wi && w0 < NW) rm0 |= mrow[w0];
            if (w1 >= wi && w1 < NW) rm1 |= mrow[w1];
            if (w2 >= wi && w2 < NW) rm2 |= mrow[w2];
        }
    }
    for (int m = count; m < POST; m++)
        if (lane < 4) out[OFF_ROIS + (n * POST + m) * 4 + lane] = 0.f;
    for (int m = lane; m < POST; m += 32)
        out[OFF_INDS + n * POST + m] = (float)n;
}

// ---------------- anchors output (f32, replicating numpy f32 arithmetic) -------------
__global__ void anchors_k(float* __restrict__ out) {
    int i = blockIdx.x * 256 + threadIdx.x;
    if (i >= PP) return;
    int cell = i / KA, k = i - cell * KA;
    int y = cell / WW, x = cell - y * WW;
    float a0, a1, a2, a3;
    anchor_ab(k, a0, a1, a2, a3);
    float sy = (float)(y * 16), sx = (float)(x * 16);
    out[OFF_ANCH + i * 4 + 0] = sy + a0;
    out[OFF_ANCH + i * 4 + 1] = sx + a1;
    out[OFF_ANCH + i * 4 + 2] = sy + a2;
    out[OFF_ANCH + i * 4 + 3] = sx + a3;
}

// ---------------- launch -------------------------------------------------------------
extern "C" void kernel_launch(void* const* d_in, const int* in_sizes, int n_in,
                              void* d_out, int out_size) {
    const float* x  = (const float*)d_in[0];
    const float* w1 = (const float*)d_in[1];
    const float* b1 = (const float*)d_in[2];
    const float* wc = (const float*)d_in[3];
    const float* bc = (const float*)d_in[4];
    const float* wr = (const float*)d_in[5];
    const float* br = (const float*)d_in[6];
    const int* imw  = (const int*)d_in[7];
    const int* imh  = (const int*)d_in[8];
    float* out = (float*)d_out;

    wtrans<<<(CI * 9 * CI + 255) / 256, 256>>>(w1);
    conv3<<<dim3(7, 25, NB * 4), 256>>>(x, b1);
    heads<<<dim3(79, NB), 128>>>(wc, bc, wr, br, out);
    decode_all<<<(NB * PP + 255) / 256, 256>>>(imw, imh);

    void *pt, *pki, *pko, *pvi, *pvo, *poff;
    cudaGetSymbolAddress(&pt,  g_cubtmp);
    cudaGetSymbolAddress(&pki, g_ki);
    cudaGetSymbolAddress(&pko, g_ko);
    cudaGetSymbolAddress(&pvi, g_vi);
    cudaGetSymbolAddress(&pvo, g_vo);
    cudaGetSymbolAddress(&poff, g_segoff);
    size_t tb = sizeof(g_cubtmp);
    cub::DeviceSegmentedRadixSort::SortPairsDescending(
        pt, tb,
        (const unsigned long long*)pki, (unsigned long long*)pko,
        (const unsigned*)pvi, (unsigned*)pvo,
        NB * PP, NB,
        (const int*)poff, (const int*)poff + 1,
        0, 64, (cudaStream_t)0);

    gather_top<<<(NB * PRE + 255) / 256, 256>>>();
    nms_mask<<<dim3(PRE, NB), 96>>>();
    nms_scan<<<NB, 32>>>(out);
    anchors_k<<<(PP + 255) / 256, 256>>>(out);
}

// round 6
// speedup vs baseline: 10.2863x; 1.4888x over previous
#include <cuda_runtime.h>
#include <cub/cub.cuh>
#include <math.h>

#define NB 8
#define CI 256
#define HH 100
#define WW 100
#define KA 9
#define PP 90000          // anchors per image
#define PRE 3000
#define POST 300
#define NW 94             // 32-bit words to cover PRE bits

#define OFF_CLS  0
#define OFF_REG  1440000
#define OFF_ROIS 4320000
#define OFF_INDS 4329600
#define OFF_ANCH 4332000

typedef unsigned long long ull;

// ---- packed f32x2 ops (sm_103a FFMA2/FADD2, PTX-only) ----
#define FMA2(d, a, b, c) asm("fma.rn.f32x2 %0, %1, %2, %3;" : "=l"(d) : "l"(a), "l"(b), "l"(c))
#define ADD2(d, a, b)    asm("add.rn.f32x2 %0, %1, %2;"     : "=l"(d) : "l"(a), "l"(b))
#define PACK2(d, lo, hi) asm("mov.b64 %0, {%1, %2};"        : "=l"(d) : "r"(__float_as_uint(lo)), "r"(__float_as_uint(hi)))
__device__ __forceinline__ void unpack2(ull v, float& lo, float& hi) {
    unsigned l, h;
    asm("mov.b64 {%0, %1}, %2;" : "=r"(l), "=r"(h) : "l"(v));
    lo = __uint_as_float(l); hi = __uint_as_float(h);
}

// ---------------- scratch (static device memory; no runtime allocation) -------------
__device__ float  g_hhi[NB*CI*HH*WW];        // conv output hi part (82 MB)
__device__ float  g_hlo[NB*CI*HH*WW];        // conv output lo part (82 MB)
__device__ float  g_w1tf[CI*9*CI];           // w1 transposed to [ic][k][oc], f32
__device__ double g_score[NB*PP];
__device__ double g_reg[NB*PP*4];            // f64 reg head output (feeds decode)
__device__ double g_boxes[NB*PP*4];
__device__ unsigned long long g_ki[NB*PP], g_ko[NB*PP];
__device__ unsigned g_vi[NB*PP], g_vo[NB*PP];
__device__ int g_segoff[9] = {0,90000,180000,270000,360000,450000,540000,630000,720000};
__device__ double g_bsort[NB*PRE*4];
__device__ double g_area[NB*PRE];
__device__ float4 g_bsf[NB*PRE];             // f32 mirror of boxes for fast IoU
__device__ float  g_areaf[NB*PRE];
__device__ int   g_valid[NB*PRE];
__device__ unsigned g_mask[NB*PRE*NW];
__device__ unsigned char g_cubtmp[48u<<20];

// ---------------- anchor base (double math, rounded to f32 = np.float32 array) ------
__device__ __forceinline__ void anchor_ab(int k, float& a0, float& a1, float& a2, float& a3) {
    int ri = k / 3, si = k % 3;
    double r = (ri == 0) ? 0.5 : ((ri == 1) ? 1.0 : 2.0);
    double s = (si == 0) ? 8.0 : ((si == 1) ? 16.0 : 32.0);
    double h = 16.0 * s * sqrt(r);
    double w = 16.0 * s * sqrt(1.0 / r);
    a0 = (float)(8.0 - h / 2.0);
    a1 = (float)(8.0 - w / 2.0);
    a2 = (float)(8.0 + h / 2.0);
    a3 = (float)(8.0 + w / 2.0);
}

// ---------------- weight transpose for conv3x3: [oc][ic][k] -> [ic][k][oc] -----------
__global__ void wtrans(const float* __restrict__ w1) {
    int idx = blockIdx.x * 256 + threadIdx.x;
    if (idx >= CI * 9 * CI) return;
    int oc = idx % CI;
    int t  = idx / CI;
    int kk = t % 9;
    int ic = t / 9;
    g_w1tf[idx] = w1[(oc * CI + ic) * 9 + kk];
}

// ------ conv 3x3, pad 1, 256->256, +bias, ReLU, packed-f32x2 compensated MACs --------
// block: 256 threads; tile: 4 rows x 16 cols x 128 oc; thread: 4 rows x 8 oc (4 pairs)
__global__ __launch_bounds__(256) void conv3(const float* __restrict__ x,
                                             const float* __restrict__ b1) {
    __shared__ float sx[8][6][18];
    __shared__ float sw[8][9][128];
    int n   = blockIdx.z >> 1;
    int ocb = (blockIdx.z & 1) * 128;
    int bx0 = blockIdx.x * 16;
    int by0 = blockIdx.y * 4;
    int tid = threadIdx.x;
    int c   = tid & 15;       // column within tile
    int g   = tid >> 4;       // 0..15, 8 oc (4 pairs) each

    const float BIAS = 96.0f;
    ull BIASP, NEG1, H[16], L[16];
    PACK2(BIASP, BIAS, BIAS);
    PACK2(NEG1, -1.0f, -1.0f);
    #pragma unroll
    for (int i = 0; i < 16; i++) { H[i] = BIASP; L[i] = 0ull; }

    for (int icb = 0; icb < CI; icb += 8) {
        for (int idx = tid; idx < 8 * 6 * 18; idx += 256) {
            int ic = idx / 108, rem = idx % 108;
            int r = rem / 18, cc = rem % 18;
            int gy = by0 + r - 1, gx = bx0 + cc - 1;
            float v = 0.f;
            if ((unsigned)gy < 100u && (unsigned)gx < 100u)
                v = x[((n * CI + icb + ic) * HH + gy) * WW + gx];
            sx[ic][r][cc] = v;
        }
        // sw: 8 ic x 9 k x 128 oc = 2304 float4 loads, layout contiguous in oc
        for (int i = tid; i < 2304; i += 256) {
            int ic = i / 288, rem = i % 288;
            int kk = rem / 32, o4 = rem % 32;
            *(float4*)&sw[ic][kk][o4 * 4] =
                *(const float4*)&g_w1tf[((icb + ic) * 9 + kk) * CI + ocb + o4 * 4];
        }
        __syncthreads();

        #pragma unroll 1
        for (int ic = 0; ic < 8; ic++) {
            #pragma unroll
            for (int ky = 0; ky < 3; ky++) {
                #pragma unroll
                for (int kx = 0; kx < 3; kx++) {
                    int k = ky * 3 + kx;
                    ull w0 = *(const ull*)&sw[ic][k][g * 8 + 0];
                    ull w1v = *(const ull*)&sw[ic][k][g * 8 + 2];
                    ull w2 = *(const ull*)&sw[ic][k][g * 8 + 4];
                    ull w3 = *(const ull*)&sw[ic][k][g * 8 + 6];
                    #pragma unroll
                    for (int r = 0; r < 4; r++) {
                        float xv = sx[ic][r + ky][c + kx];
                        ull xx; PACK2(xx, xv, xv);
                        ull Hn, nd, rr;
                        #pragma unroll
                        for (int p = 0; p < 4; p++) {
                            ull wp = (p == 0) ? w0 : ((p == 1) ? w1v : ((p == 2) ? w2 : w3));
                            int a = r * 4 + p;
                            FMA2(Hn, xx, wp, H[a]);
                            FMA2(nd, Hn, NEG1, H[a]);   // = H - Hn (exact)
                            FMA2(rr, xx, wp, nd);       // = x*w - (Hn - H)
                            ADD2(L[a], L[a], rr);
                            H[a] = Hn;
                        }
                    }
                }
            }
        }
        __syncthreads();
    }

    // epilogue: rows always in-bounds (by0 <= 96), guard columns
    int gx = bx0 + c;
    if (gx < WW) {
        #pragma unroll
        for (int r = 0; r < 4; r++) {
            #pragma unroll
            for (int p = 0; p < 4; p++) {
                float h0, h1, l0, l1;
                unpack2(H[r * 4 + p], h0, h1);
                unpack2(L[r * 4 + p], l0, l1);
                int oc = ocb + g * 8 + p * 2;
                int gy = by0 + r;
                size_t o0 = ((size_t)(n * CI + oc) * HH + gy) * WW + gx;
                double v0 = (double)__fsub_rn(h0, BIAS) + (double)l0 + (double)b1[oc];
                v0 = fmax(v0, 0.0);
                float vh0 = (float)v0;
                g_hhi[o0] = vh0;
                g_hlo[o0] = (float)(v0 - (double)vh0);
                size_t o1 = o0 + (size_t)HH * WW;
                double v1 = (double)__fsub_rn(h1, BIAS) + (double)l1 + (double)b1[oc + 1];
                v1 = fmax(v1, 0.0);
                float vh1 = (float)v1;
                g_hhi[o1] = vh1;
                g_hlo[o1] = (float)(v1 - (double)vh1);
            }
        }
    }
}

// ------- fused 1x1 heads (18 cls + 36 reg), packed-f32x2 compensated -----------------
__global__ __launch_bounds__(128) void heads(const float* __restrict__ wc,
                                             const float* __restrict__ bc,
                                             const float* __restrict__ wr,
                                             const float* __restrict__ br,
                                             float* __restrict__ out) {
    __shared__ float sw1[64][54];
    int n = blockIdx.y;
    int p = blockIdx.x * 128 + threadIdx.x;   // pixel id

    const float BIAS = 16.0f;
    ull BIASP, NEG1, H[27], L[27];
    PACK2(BIASP, BIAS, BIAS);
    PACK2(NEG1, -1.0f, -1.0f);
    #pragma unroll
    for (int o = 0; o < 27; o++) { H[o] = BIASP; L[o] = 0ull; }

    for (int icb = 0; icb < CI; icb += 64) {
        for (int idx = threadIdx.x; idx < 64 * 54; idx += 128) {
            int ic = idx / 54, oc = idx % 54;
            sw1[ic][oc] = (oc < 18) ? wc[oc * CI + icb + ic]
                                    : wr[(oc - 18) * CI + icb + ic];
        }
        __syncthreads();
        if (p < HH * WW) {
            #pragma unroll 1
            for (int ic = 0; ic < 64; ic++) {
                size_t o = (size_t)(n * CI + icb + ic) * (HH * WW) + p;
                float hh = g_hhi[o];
                float hl = g_hlo[o];
                ull hhp, hlp;
                PACK2(hhp, hh, hh);
                PACK2(hlp, hl, hl);
                #pragma unroll
                for (int q = 0; q < 27; q++) {
                    ull wp = *(const ull*)&sw1[ic][q * 2];
                    ull Hn, nd, rr;
                    FMA2(Hn, hhp, wp, H[q]);
                    FMA2(nd, Hn, NEG1, H[q]);
                    FMA2(rr, hhp, wp, nd);
                    ADD2(L[q], L[q], rr);
                    FMA2(L[q], hlp, wp, L[q]);   // lo-part contribution
                    H[q] = Hn;
                }
            }
        }
        __syncthreads();
    }
    if (p >= HH * WW) return;

    float hs[54], ls[54];
    #pragma unroll
    for (int q = 0; q < 27; q++) {
        unpack2(H[q], hs[q * 2], hs[q * 2 + 1]);
        unpack2(L[q], ls[q * 2], ls[q * 2 + 1]);
    }

    double l[18];
    #pragma unroll
    for (int c18 = 0; c18 < 18; c18++) {
        l[c18] = (double)__fsub_rn(hs[c18], BIAS) + (double)ls[c18] + (double)bc[c18];
        int k = c18 >> 1, cc = c18 & 1;
        out[OFF_CLS + (n * 2 + cc) * PP + p * KA + k] = (float)l[c18];
    }
    #pragma unroll
    for (int k = 0; k < KA; k++) {
        double s = 1.0 / (1.0 + exp(l[2 * k] - l[2 * k + 1]));
        g_score[n * PP + p * KA + k] = s;
    }
    #pragma unroll
    for (int c36 = 0; c36 < 36; c36++) {
        int k = c36 >> 2, j = c36 & 3;
        double v = (double)__fsub_rn(hs[18 + c36], BIAS) + (double)ls[18 + c36]
                 + (double)br[c36];
        out[OFF_REG + n * (PP * 4) + (p * KA + k) * 4 + j] = (float)v;
        g_reg[(size_t)n * (PP * 4) + (p * KA + k) * 4 + j] = v;
    }
}

// ---------------- decode all anchors, clip, min-size, build f64-bit sort keys --------
__global__ void decode_all(const int* __restrict__ pimw,
                           const int* __restrict__ pimh) {
    int idx = blockIdx.x * 256 + threadIdx.x;
    if (idx >= NB * PP) return;
    int n = idx / PP, i = idx - n * PP;
    int cell = i / KA, k = i - cell * KA;
    int y = cell / WW, x = cell - y * WW;

    float a0, a1, a2, a3;
    anchor_ab(k, a0, a1, a2, a3);
    float sy = (float)(y * 16), sx0 = (float)(x * 16);
    float af0 = sy + a0, af1 = sx0 + a1, af2 = sy + a2, af3 = sx0 + a3;
    float ahf = af2 - af0, awf = af3 - af1;
    float ayf = af0 + 0.5f * ahf, axf = af1 + 0.5f * awf;
    double ah = (double)ahf, aw = (double)awf, ay = (double)ayf, ax = (double)axf;

    const double* lp = &g_reg[(size_t)n * (PP * 4) + (size_t)i * 4];
    double dy = lp[0], dx = lp[1], dh = lp[2], dw = lp[3];
    double cy = dy * ah + ay, cx = dx * aw + ax;
    double hb = exp(dh) * ah, wb = exp(dw) * aw;

    int wv = pimw[0], hv = pimh[0];
    double imw = (wv > 65536 || wv < 0) ? (double)__int_as_float(wv) : (double)wv;
    double imh = (hv > 65536 || hv < 0) ? (double)__int_as_float(hv) : (double)hv;

    double y1 = fmin(fmax(cy - 0.5 * hb, 0.0), imh);
    double y2 = fmin(fmax(cy + 0.5 * hb, 0.0), imh);
    double x1 = fmin(fmax(cx - 0.5 * wb, 0.0), imw);
    double x2 = fmin(fmax(cx + 0.5 * wb, 0.0), imw);
    bool big = (y2 - y1 >= 16.0) && (x2 - x1 >= 16.0);

    double* bp = &g_boxes[(size_t)idx * 4];
    bp[0] = y1; bp[1] = x1; bp[2] = y2; bp[3] = x2;

    g_ki[idx] = big ? __double_as_longlong(g_score[idx]) : 0ull;
    g_vi[idx] = (unsigned)i;
}

// ---------------- gather top PRE per batch ------------------------------------------
__global__ void gather_top() {
    int idx = blockIdx.x * 256 + threadIdx.x;
    if (idx >= NB * PRE) return;
    int n = idx / PRE, r = idx - n * PRE;
    unsigned long long key = g_ko[n * PP + r];
    unsigned i = g_vo[n * PP + r];
    const double* bp = &g_boxes[((size_t)n * PP + i) * 4];
    double y1 = bp[0], x1 = bp[1], y2 = bp[2], x2 = bp[3];
    double* d = &g_bsort[(size_t)idx * 4];
    d[0] = y1; d[1] = x1; d[2] = y2; d[3] = x2;
    double a = (y2 - y1) * (x2 - x1);
    g_area[idx]  = a;
    g_bsf[idx]   = make_float4((float)y1, (float)x1, (float)y2, (float)x2);
    g_areaf[idx] = (float)a;
    g_valid[idx] = (key != 0ull) ? 1 : 0;
}

// ------- NMS mask: f32 IoU with f64 fallback in a guard band around the threshold ----
__global__ __launch_bounds__(96) void nms_mask() {
    int i = blockIdx.x, n = blockIdx.y;
    float4 bi = g_bsf[n * PRE + i];
    float ai = g_areaf[n * PRE + i];
    int lane = threadIdx.x & 31, wp = threadIdx.x >> 5;
    int wstart = i >> 5;
    for (int w = wstart + wp; w < NW; w += 3) {
        int j = w * 32 + lane;
        bool bit = false;
        if (j < PRE && j > i) {
            float4 bj = g_bsf[n * PRE + j];
            float yy1 = fmaxf(bi.x, bj.x);
            float xx1 = fmaxf(bi.y, bj.y);
            float yy2 = fminf(bi.z, bj.z);
            float xx2 = fminf(bi.w, bj.w);
            float inter = fmaxf(yy2 - yy1, 0.f) * fmaxf(xx2 - xx1, 0.f);
            float iou = inter / (ai + g_areaf[n * PRE + j] - inter + 1e-9f);
            if (fabsf(iou - 0.7f) < 1e-4f) {
                const double* di = &g_bsort[((size_t)n * PRE + i) * 4];
                const double* dj = &g_bsort[((size_t)n * PRE + j) * 4];
                double dy1 = fmax(di[0], dj[0]);
                double dx1 = fmax(di[1], dj[1]);
                double dy2 = fmin(di[2], dj[2]);
                double dx2 = fmin(di[3], dj[3]);
                double dint = fmax(dy2 - dy1, 0.0) * fmax(dx2 - dx1, 0.0);
                double diou = dint / (g_area[n * PRE + i] + g_area[n * PRE + j]
                                      - dint + 1e-9);
                bit = diou > 0.7;
            } else {
                bit = iou > 0.7f;
            }
        }
        unsigned m = __ballot_sync(0xffffffffu, bit);
        if (lane == 0) g_mask[((size_t)n * PRE + i) * NW + w] = m;
    }
}

// ---------------- serial greedy scan, 1 warp per batch, write rois + inds ------------
__global__ __launch_bounds__(32) void nms_scan(float* __restrict__ out) {
    int n = blockIdx.x;
    int lane = threadIdx.x;
    unsigned rm0 = 0, rm1 = 0, rm2 = 0;   // lane holds words lane, lane+32, lane+64
    int count = 0;
    for (int i = 0; i < PRE && count < POST; i++) {
        int wi = i >> 5;
        int slot = wi >> 5;
        int src  = wi & 31;
        unsigned myw = (slot == 0) ? rm0 : ((slot == 1) ? rm1 : rm2);
        unsigned word = __shfl_sync(0xffffffffu, myw, src);
        bool kept = g_valid[n * PRE + i] && !((word >> (i & 31)) & 1u);
        if (kept) {
            if (lane < 4)
                out[OFF_ROIS + (n * POST + count) * 4 + lane] =
                    (float)g_bsort[((size_t)n * PRE + i) * 4 + lane];
            count++;
            const unsigned* mrow = &g_mask[((size_t)n * PRE + i) * NW];
            int w0 = lane;
            int w1 = lane + 32;
            int w2 = lane + 64;
            if (w0 >= wi && w0 < NW) rm0 |= mrow[w0];
            if (w1 >= wi && w1 < NW) rm1 |= mrow[w1];
            if (w2 >= wi && w2 < NW) rm2 |= mrow[w2];
        }
    }
    for (int m = count; m < POST; m++)
        if (lane < 4) out[OFF_ROIS + (n * POST + m) * 4 + lane] = 0.f;
    for (int m = lane; m < POST; m += 32)
        out[OFF_INDS + n * POST + m] = (float)n;
}

// ---------------- anchors output (f32, replicating numpy f32 arithmetic) -------------
__global__ void anchors_k(float* __restrict__ out) {
    int i = blockIdx.x * 256 + threadIdx.x;
    if (i >= PP) return;
    int cell = i / KA, k = i - cell * KA;
    int y = cell / WW, x = cell - y * WW;
    float a0, a1, a2, a3;
    anchor_ab(k, a0, a1, a2, a3);
    float sy = (float)(y * 16), sx = (float)(x * 16);
    out[OFF_ANCH + i * 4 + 0] = sy + a0;
    out[OFF_ANCH + i * 4 + 1] = sx + a1;
    out[OFF_ANCH + i * 4 + 2] = sy + a2;
    out[OFF_ANCH + i * 4 + 3] = sx + a3;
}

// ---------------- launch -------------------------------------------------------------
extern "C" void kernel_launch(void* const* d_in, const int* in_sizes, int n_in,
                              void* d_out, int out_size) {
    const float* x  = (const float*)d_in[0];
    const float* w1 = (const float*)d_in[1];
    const float* b1 = (const float*)d_in[2];
    const float* wc = (const float*)d_in[3];
    const float* bc = (const float*)d_in[4];
    const float* wr = (const float*)d_in[5];
    const float* br = (const float*)d_in[6];
    const int* imw  = (const int*)d_in[7];
    const int* imh  = (const int*)d_in[8];
    float* out = (float*)d_out;

    wtrans<<<(CI * 9 * CI + 255) / 256, 256>>>(w1);
    conv3<<<dim3(7, 25, NB * 2), 256>>>(x, b1);
    heads<<<dim3(79, NB), 128>>>(wc, bc, wr, br, out);
    decode_all<<<(NB * PP + 255) / 256, 256>>>(imw, imh);

    void *pt, *pki, *pko, *pvi, *pvo, *poff;
    cudaGetSymbolAddress(&pt,  g_cubtmp);
    cudaGetSymbolAddress(&pki, g_ki);
    cudaGetSymbolAddress(&pko, g_ko);
    cudaGetSymbolAddress(&pvi, g_vi);
    cudaGetSymbolAddress(&pvo, g_vo);
    cudaGetSymbolAddress(&poff, g_segoff);
    size_t tb = sizeof(g_cubtmp);
    cub::DeviceSegmentedRadixSort::SortPairsDescending(
        pt, tb,
        (const unsigned long long*)pki, (unsigned long long*)pko,
        (const unsigned*)pvi, (unsigned*)pvo,
        NB * PP, NB,
        (const int*)poff, (const int*)poff + 1,
        0, 64, (cudaStream_t)0);

    gather_top<<<(NB * PRE + 255) / 256, 256>>>();
    nms_mask<<<dim3(PRE, NB), 96>>>();
    nms_scan<<<NB, 32>>>(out);
    anchors_k<<<(PP + 255) / 256, 256>>>(out);
}

// round 7
// speedup vs baseline: 10.3032x; 1.0016x over previous
#include <cuda_runtime.h>
#include <cub/cub.cuh>
#include <math.h>

#define NB 8
#define CI 256
#define HH 100
#define WW 100
#define KA 9
#define PP 90000          // anchors per image
#define PRE 3000
#define POST 300
#define NW 94             // 32-bit words to cover PRE bits

#define OFF_CLS  0
#define OFF_REG  1440000
#define OFF_ROIS 4320000
#define OFF_INDS 4329600
#define OFF_ANCH 4332000

typedef unsigned long long ull;

// ---- packed f32x2 ops (sm_103a FFMA2/FADD2, PTX-only) ----
#define FMA2(d, a, b, c) asm("fma.rn.f32x2 %0, %1, %2, %3;" : "=l"(d) : "l"(a), "l"(b), "l"(c))
#define ADD2(d, a, b)    asm("add.rn.f32x2 %0, %1, %2;"     : "=l"(d) : "l"(a), "l"(b))
#define PACK2(d, lo, hi) asm("mov.b64 %0, {%1, %2};"        : "=l"(d) : "r"(__float_as_uint(lo)), "r"(__float_as_uint(hi)))
__device__ __forceinline__ void unpack2(ull v, float& lo, float& hi) {
    unsigned l, h;
    asm("mov.b64 {%0, %1}, %2;" : "=r"(l), "=r"(h) : "l"(v));
    lo = __uint_as_float(l); hi = __uint_as_float(h);
}

// ---------------- scratch (static device memory; no runtime allocation) -------------
__device__ float  g_hhi[NB*CI*HH*WW];        // conv output hi part (82 MB)
__device__ float  g_hlo[NB*CI*HH*WW];        // conv output lo part (82 MB)
__device__ float  g_w1tf[CI*9*CI];           // w1 transposed to [ic][k][oc], f32
__device__ double g_score[NB*PP];
__device__ double g_reg[NB*PP*4];            // f64 reg head output (feeds decode)
__device__ double g_boxes[NB*PP*4];
__device__ unsigned long long g_ki[NB*PP], g_ko[NB*PP];
__device__ unsigned g_vi[NB*PP], g_vo[NB*PP];
__device__ int g_segoff[9] = {0,90000,180000,270000,360000,450000,540000,630000,720000};
__device__ double g_bsort[NB*PRE*4];
__device__ double g_area[NB*PRE];
__device__ float4 g_bsf[NB*PRE];             // f32 mirror of boxes for fast IoU
__device__ float  g_areaf[NB*PRE];
__device__ int   g_valid[NB*PRE];
__device__ unsigned g_mask[NB*PRE*NW];
__device__ unsigned char g_cubtmp[48u<<20];

// ---------------- anchor base (double math, rounded to f32 = np.float32 array) ------
__device__ __forceinline__ void anchor_ab(int k, float& a0, float& a1, float& a2, float& a3) {
    int ri = k / 3, si = k % 3;
    double r = (ri == 0) ? 0.5 : ((ri == 1) ? 1.0 : 2.0);
    double s = (si == 0) ? 8.0 : ((si == 1) ? 16.0 : 32.0);
    double h = 16.0 * s * sqrt(r);
    double w = 16.0 * s * sqrt(1.0 / r);
    a0 = (float)(8.0 - h / 2.0);
    a1 = (float)(8.0 - w / 2.0);
    a2 = (float)(8.0 + h / 2.0);
    a3 = (float)(8.0 + w / 2.0);
}

// ---------------- weight transpose for conv3x3: [oc][ic][k] -> [ic][k][oc] -----------
__global__ void wtrans(const float* __restrict__ w1) {
    int idx = blockIdx.x * 256 + threadIdx.x;
    if (idx >= CI * 9 * CI) return;
    int oc = idx % CI;
    int t  = idx / CI;
    int kk = t % 9;
    int ic = t / 9;
    g_w1tf[idx] = w1[(oc * CI + ic) * 9 + kk];
}

// ------ conv 3x3, pad 1, 256->256, +bias, ReLU, packed-f32x2 compensated MACs --------
// block: 256 threads; tile: 4 rows x 16 cols x 128 oc; thread: 4 rows x 8 oc (4 pairs)
__global__ __launch_bounds__(256) void conv3(const float* __restrict__ x,
                                             const float* __restrict__ b1) {
    __shared__ float sx[8][6][18];
    __shared__ float sw[8][9][128];
    int n   = blockIdx.z >> 1;
    int ocb = (blockIdx.z & 1) * 128;
    int bx0 = blockIdx.x * 16;
    int by0 = blockIdx.y * 4;
    int tid = threadIdx.x;
    int c   = tid & 15;       // column within tile
    int g   = tid >> 4;       // 0..15, 8 oc (4 pairs) each

    const float BIAS = 96.0f;
    ull BIASP, NEG1, H[16], L[16];
    PACK2(BIASP, BIAS, BIAS);
    PACK2(NEG1, -1.0f, -1.0f);
    #pragma unroll
    for (int i = 0; i < 16; i++) { H[i] = BIASP; L[i] = 0ull; }

    for (int icb = 0; icb < CI; icb += 8) {
        for (int idx = tid; idx < 8 * 6 * 18; idx += 256) {
            int ic = idx / 108, rem = idx % 108;
            int r = rem / 18, cc = rem % 18;
            int gy = by0 + r - 1, gx = bx0 + cc - 1;
            float v = 0.f;
            if ((unsigned)gy < 100u && (unsigned)gx < 100u)
                v = x[((n * CI + icb + ic) * HH + gy) * WW + gx];
            sx[ic][r][cc] = v;
        }
        // sw: 8 ic x 9 k x 128 oc = 2304 float4 loads, layout contiguous in oc
        for (int i = tid; i < 2304; i += 256) {
            int ic = i / 288, rem = i % 288;
            int kk = rem / 32, o4 = rem % 32;
            *(float4*)&sw[ic][kk][o4 * 4] =
                *(const float4*)&g_w1tf[((icb + ic) * 9 + kk) * CI + ocb + o4 * 4];
        }
        __syncthreads();

        #pragma unroll 1
        for (int ic = 0; ic < 8; ic++) {
            #pragma unroll
            for (int ky = 0; ky < 3; ky++) {
                #pragma unroll
                for (int kx = 0; kx < 3; kx++) {
                    int k = ky * 3 + kx;
                    ull w0 = *(const ull*)&sw[ic][k][g * 8 + 0];
                    ull w1v = *(const ull*)&sw[ic][k][g * 8 + 2];
                    ull w2 = *(const ull*)&sw[ic][k][g * 8 + 4];
                    ull w3 = *(const ull*)&sw[ic][k][g * 8 + 6];
                    #pragma unroll
                    for (int r = 0; r < 4; r++) {
                        float xv = sx[ic][r + ky][c + kx];
                        ull xx; PACK2(xx, xv, xv);
                        ull Hn, nd, rr;
                        #pragma unroll
                        for (int p = 0; p < 4; p++) {
                            ull wp = (p == 0) ? w0 : ((p == 1) ? w1v : ((p == 2) ? w2 : w3));
                            int a = r * 4 + p;
                            FMA2(Hn, xx, wp, H[a]);
                            FMA2(nd, Hn, NEG1, H[a]);   // = H - Hn (exact)
                            FMA2(rr, xx, wp, nd);       // = x*w - (Hn - H)
                            ADD2(L[a], L[a], rr);
                            H[a] = Hn;
                        }
                    }
                }
            }
        }
        __syncthreads();
    }

    // epilogue: rows always in-bounds (by0 <= 96), guard columns
    int gx = bx0 + c;
    if (gx < WW) {
        #pragma unroll
        for (int r = 0; r < 4; r++) {
            #pragma unroll
            for (int p = 0; p < 4; p++) {
                float h0, h1, l0, l1;
                unpack2(H[r * 4 + p], h0, h1);
                unpack2(L[r * 4 + p], l0, l1);
                int oc = ocb + g * 8 + p * 2;
                int gy = by0 + r;
                size_t o0 = ((size_t)(n * CI + oc) * HH + gy) * WW + gx;
                double v0 = (double)__fsub_rn(h0, BIAS) + (double)l0 + (double)b1[oc];
                v0 = fmax(v0, 0.0);
                float vh0 = (float)v0;
                g_hhi[o0] = vh0;
                g_hlo[o0] = (float)(v0 - (double)vh0);
                size_t o1 = o0 + (size_t)HH * WW;
                double v1 = (double)__fsub_rn(h1, BIAS) + (double)l1 + (double)b1[oc + 1];
                v1 = fmax(v1, 0.0);
                float vh1 = (float)v1;
                g_hhi[o1] = vh1;
                g_hlo[o1] = (float)(v1 - (double)vh1);
            }
        }
    }
}

// ------- fused 1x1 heads (18 cls + 36 reg), packed-f32x2 compensated -----------------
__global__ __launch_bounds__(128) void heads(const float* __restrict__ wc,
                                             const float* __restrict__ bc,
                                             const float* __restrict__ wr,
                                             const float* __restrict__ br,
                                             float* __restrict__ out) {
    __shared__ float sw1[64][54];
    int n = blockIdx.y;
    int p = blockIdx.x * 128 + threadIdx.x;   // pixel id

    const float BIAS = 16.0f;
    ull BIASP, NEG1, H[27], L[27];
    PACK2(BIASP, BIAS, BIAS);
    PACK2(NEG1, -1.0f, -1.0f);
    #pragma unroll
    for (int o = 0; o < 27; o++) { H[o] = BIASP; L[o] = 0ull; }

    for (int icb = 0; icb < CI; icb += 64) {
        for (int idx = threadIdx.x; idx < 64 * 54; idx += 128) {
            int ic = idx / 54, oc = idx % 54;
            sw1[ic][oc] = (oc < 18) ? wc[oc * CI + icb + ic]
                                    : wr[(oc - 18) * CI + icb + ic];
        }
        __syncthreads();
        if (p < HH * WW) {
            #pragma unroll 1
            for (int ic = 0; ic < 64; ic++) {
                size_t o = (size_t)(n * CI + icb + ic) * (HH * WW) + p;
                float hh = g_hhi[o];
                float hl = g_hlo[o];
                ull hhp, hlp;
                PACK2(hhp, hh, hh);
                PACK2(hlp, hl, hl);
                #pragma unroll
                for (int q = 0; q < 27; q++) {
                    ull wp = *(const ull*)&sw1[ic][q * 2];
                    ull Hn, nd, rr;
                    FMA2(Hn, hhp, wp, H[q]);
                    FMA2(nd, Hn, NEG1, H[q]);
                    FMA2(rr, hhp, wp, nd);
                    ADD2(L[q], L[q], rr);
                    FMA2(L[q], hlp, wp, L[q]);   // lo-part contribution
                    H[q] = Hn;
                }
            }
        }
        __syncthreads();
    }
    if (p >= HH * WW) return;

    float hs[54], ls[54];
    #pragma unroll
    for (int q = 0; q < 27; q++) {
        unpack2(H[q], hs[q * 2], hs[q * 2 + 1]);
        unpack2(L[q], ls[q * 2], ls[q * 2 + 1]);
    }

    double l[18];
    #pragma unroll
    for (int c18 = 0; c18 < 18; c18++) {
        l[c18] = (double)__fsub_rn(hs[c18], BIAS) + (double)ls[c18] + (double)bc[c18];
        int k = c18 >> 1, cc = c18 & 1;
        out[OFF_CLS + (n * 2 + cc) * PP + p * KA + k] = (float)l[c18];
    }
    #pragma unroll
    for (int k = 0; k < KA; k++) {
        double s = 1.0 / (1.0 + exp(l[2 * k] - l[2 * k + 1]));
        g_score[n * PP + p * KA + k] = s;
    }
    #pragma unroll
    for (int c36 = 0; c36 < 36; c36++) {
        int k = c36 >> 2, j = c36 & 3;
        double v = (double)__fsub_rn(hs[18 + c36], BIAS) + (double)ls[18 + c36]
                 + (double)br[c36];
        out[OFF_REG + n * (PP * 4) + (p * KA + k) * 4 + j] = (float)v;
        g_reg[(size_t)n * (PP * 4) + (p * KA + k) * 4 + j] = v;
    }
}

// ---------------- decode all anchors, clip, min-size, build f64-bit sort keys --------
__global__ void decode_all(const int* __restrict__ pimw,
                           const int* __restrict__ pimh) {
    int idx = blockIdx.x * 256 + threadIdx.x;
    if (idx >= NB * PP) return;
    int n = idx / PP, i = idx - n * PP;
    int cell = i / KA, k = i - cell * KA;
    int y = cell / WW, x = cell - y * WW;

    float a0, a1, a2, a3;
    anchor_ab(k, a0, a1, a2, a3);
    float sy = (float)(y * 16), sx0 = (float)(x * 16);
    float af0 = sy + a0, af1 = sx0 + a1, af2 = sy + a2, af3 = sx0 + a3;
    float ahf = af2 - af0, awf = af3 - af1;
    float ayf = af0 + 0.5f * ahf, axf = af1 + 0.5f * awf;
    double ah = (double)ahf, aw = (double)awf, ay = (double)ayf, ax = (double)axf;

    const double* lp = &g_reg[(size_t)n * (PP * 4) + (size_t)i * 4];
    double dy = lp[0], dx = lp[1], dh = lp[2], dw = lp[3];
    double cy = dy * ah + ay, cx = dx * aw + ax;
    double hb = exp(dh) * ah, wb = exp(dw) * aw;

    int wv = pimw[0], hv = pimh[0];
    double imw = (wv > 65536 || wv < 0) ? (double)__int_as_float(wv) : (double)wv;
    double imh = (hv > 65536 || hv < 0) ? (double)__int_as_float(hv) : (double)hv;

    double y1 = fmin(fmax(cy - 0.5 * hb, 0.0), imh);
    double y2 = fmin(fmax(cy + 0.5 * hb, 0.0), imh);
    double x1 = fmin(fmax(cx - 0.5 * wb, 0.0), imw);
    double x2 = fmin(fmax(cx + 0.5 * wb, 0.0), imw);
    bool big = (y2 - y1 >= 16.0) && (x2 - x1 >= 16.0);

    double* bp = &g_boxes[(size_t)idx * 4];
    bp[0] = y1; bp[1] = x1; bp[2] = y2; bp[3] = x2;

    g_ki[idx] = big ? __double_as_longlong(g_score[idx]) : 0ull;
    g_vi[idx] = (unsigned)i;
}

// ---------------- gather top PRE per batch ------------------------------------------
__global__ void gather_top() {
    int idx = blockIdx.x * 256 + threadIdx.x;
    if (idx >= NB * PRE) return;
    int n = idx / PRE, r = idx - n * PRE;
    unsigned long long key = g_ko[n * PP + r];
    unsigned i = g_vo[n * PP + r];
    const double* bp = &g_boxes[((size_t)n * PP + i) * 4];
    double y1 = bp[0], x1 = bp[1], y2 = bp[2], x2 = bp[3];
    double* d = &g_bsort[(size_t)idx * 4];
    d[0] = y1; d[1] = x1; d[2] = y2; d[3] = x2;
    double a = (y2 - y1) * (x2 - x1);
    g_area[idx]  = a;
    g_bsf[idx]   = make_float4((float)y1, (float)x1, (float)y2, (float)x2);
    g_areaf[idx] = (float)a;
    g_valid[idx] = (key != 0ull) ? 1 : 0;
}

// ------- NMS mask: f32 IoU with f64 fallback in a guard band around the threshold ----
__global__ __launch_bounds__(96) void nms_mask() {
    int i = blockIdx.x, n = blockIdx.y;
    float4 bi = g_bsf[n * PRE + i];
    float ai = g_areaf[n * PRE + i];
    int lane = threadIdx.x & 31, wp = threadIdx.x >> 5;
    int wstart = i >> 5;
    for (int w = wstart + wp; w < NW; w += 3) {
        int j = w * 32 + lane;
        bool bit = false;
        if (j < PRE && j > i) {
            float4 bj = g_bsf[n * PRE + j];
            float yy1 = fmaxf(bi.x, bj.x);
            float xx1 = fmaxf(bi.y, bj.y);
            float yy2 = fminf(bi.z, bj.z);
            float xx2 = fminf(bi.w, bj.w);
            float inter = fmaxf(yy2 - yy1, 0.f) * fmaxf(xx2 - xx1, 0.f);
            float iou = inter / (ai + g_areaf[n * PRE + j] - inter + 1e-9f);
            if (fabsf(iou - 0.7f) < 1e-4f) {
                const double* di = &g_bsort[((size_t)n * PRE + i) * 4];
                const double* dj = &g_bsort[((size_t)n * PRE + j) * 4];
                double dy1 = fmax(di[0], dj[0]);
                double dx1 = fmax(di[1], dj[1]);
                double dy2 = fmin(di[2], dj[2]);
                double dx2 = fmin(di[3], dj[3]);
                double dint = fmax(dy2 - dy1, 0.0) * fmax(dx2 - dx1, 0.0);
                double diou = dint / (g_area[n * PRE + i] + g_area[n * PRE + j]
                                      - dint + 1e-9);
                bit = diou > 0.7;
            } else {
                bit = iou > 0.7f;
            }
        }
        unsigned m = __ballot_sync(0xffffffffu, bit);
        if (lane == 0) g_mask[((size_t)n * PRE + i) * NW + w] = m;
    }
}

// ---------------- serial greedy scan, 1 warp per batch, write rois + inds ------------
__global__ __launch_bounds__(32) void nms_scan(float* __restrict__ out) {
    int n = blockIdx.x;
    int lane = threadIdx.x;
    unsigned rm0 = 0, rm1 = 0, rm2 = 0;   // lane holds words lane, lane+32, lane+64
    int count = 0;
    for (int i = 0; i < PRE && count < POST; i++) {
        int wi = i >> 5;
        int slot = wi >> 5;
        int src  = wi & 31;
        unsigned myw = (slot == 0) ? rm0 : ((slot == 1) ? rm1 : rm2);
        unsigned word = __shfl_sync(0xffffffffu, myw, src);
        bool kept = g_valid[n * PRE + i] && !((word >> (i & 31)) & 1u);
        if (kept) {
            if (lane < 4)
                out[OFF_ROIS + (n * POST + count) * 4 + lane] =
                    (float)g_bsort[((size_t)n * PRE + i) * 4 + lane];
            count++;
            const unsigned* mrow = &g_mask[((size_t)n * PRE + i) * NW];
            int w0 = lane;
            int w1 = lane + 32;
            int w2 = lane + 64;
            if (w0 >= wi && w0 < NW) rm0 |= mrow[w0];
            if (w1 >= wi && w1 < NW) rm1 |= mrow[w1];
            if (w2 >= wi && w2 < NW) rm2 |= mrow[w2];
        }
    }
    for (int m = count; m < POST; m++)
        if (lane < 4) out[OFF_ROIS + (n * POST + m) * 4 + lane] = 0.f;
    for (int m = lane; m < POST; m += 32)
        out[OFF_INDS + n * POST + m] = (float)n;
}

// ---------------- anchors output (f32, replicating numpy f32 arithmetic) -------------
__global__ void anchors_k(float* __restrict__ out) {
    int i = blockIdx.x * 256 + threadIdx.x;
    if (i >= PP) return;
    int cell = i / KA, k = i - cell * KA;
    int y = cell / WW, x = cell - y * WW;
    float a0, a1, a2, a3;
    anchor_ab(k, a0, a1, a2, a3);
    float sy = (float)(y * 16), sx = (float)(x * 16);
    out[OFF_ANCH + i * 4 + 0] = sy + a0;
    out[OFF_ANCH + i * 4 + 1] = sx + a1;
    out[OFF_ANCH + i * 4 + 2] = sy + a2;
    out[OFF_ANCH + i * 4 + 3] = sx + a3;
}

// ---------------- launch -------------------------------------------------------------
extern "C" void kernel_launch(void* const* d_in, const int* in_sizes, int n_in,
                              void* d_out, int out_size) {
    const float* x  = (const float*)d_in[0];
    const float* w1 = (const float*)d_in[1];
    const float* b1 = (const float*)d_in[2];
    const float* wc = (const float*)d_in[3];
    const float* bc = (const float*)d_in[4];
    const float* wr = (const float*)d_in[5];
    const float* br = (const float*)d_in[6];
    const int* imw  = (const int*)d_in[7];
    const int* imh  = (const int*)d_in[8];
    float* out = (float*)d_out;

    wtrans<<<(CI * 9 * CI + 255) / 256, 256>>>(w1);
    conv3<<<dim3(7, 25, NB * 2), 256>>>(x, b1);
    heads<<<dim3(79, NB), 128>>>(wc, bc, wr, br, out);
    decode_all<<<(NB * PP + 255) / 256, 256>>>(imw, imh);

    void *pt, *pki, *pko, *pvi, *pvo, *poff;
    cudaGetSymbolAddress(&pt,  g_cubtmp);
    cudaGetSymbolAddress(&pki, g_ki);
    cudaGetSymbolAddress(&pko, g_ko);
    cudaGetSymbolAddress(&pvi, g_vi);
    cudaGetSymbolAddress(&pvo, g_vo);
    cudaGetSymbolAddress(&poff, g_segoff);
    size_t tb = sizeof(g_cubtmp);
    cub::DeviceSegmentedRadixSort::SortPairsDescending(
        pt, tb,
        (const unsigned long long*)pki, (unsigned long long*)pko,
        (const unsigned*)pvi, (unsigned*)pvo,
        NB * PP, NB,
        (const int*)poff, (const int*)poff + 1,
        0, 64, (cudaStream_t)0);

    gather_top<<<(NB * PRE + 255) / 256, 256>>>();
    nms_mask<<<dim3(PRE, NB), 96>>>();
    nms_scan<<<NB, 32>>>(out);
    anchors_k<<<(PP + 255) / 256, 256>>>(out);
}

// round 8
// speedup vs baseline: 18.8357x; 1.8281x over previous
#include <cuda_runtime.h>
#include <cub/cub.cuh>
#include <math.h>

#define NB 8
#define CI 256
#define HH 100
#define WW 100
#define KA 9
#define PP 90000          // anchors per image
#define PRE 3000
#define POST 300
#define NW 94             // 32-bit words to cover PRE bits
#define CAND 3328         // preselected candidates per image (>= PRE + margin)

#define OFF_CLS  0
#define OFF_REG  1440000
#define OFF_ROIS 4320000
#define OFF_INDS 4329600
#define OFF_ANCH 4332000

typedef unsigned long long ull;

// ---- packed f32x2 ops (sm_103a FFMA2/FADD2, PTX-only) ----
#define FMA2(d, a, b, c) asm("fma.rn.f32x2 %0, %1, %2, %3;" : "=l"(d) : "l"(a), "l"(b), "l"(c))
#define ADD2(d, a, b)    asm("add.rn.f32x2 %0, %1, %2;"     : "=l"(d) : "l"(a), "l"(b))
#define PACK2(d, lo, hi) asm("mov.b64 %0, {%1, %2};"        : "=l"(d) : "r"(__float_as_uint(lo)), "r"(__float_as_uint(hi)))
__device__ __forceinline__ void unpack2(ull v, float& lo, float& hi) {
    unsigned l, h;
    asm("mov.b64 {%0, %1}, %2;" : "=r"(l), "=r"(h) : "l"(v));
    lo = __uint_as_float(l); hi = __uint_as_float(h);
}

// ---- scalar compensated MAC (Dekker 2Prod + Fast2Sum with biased accumulator) ----
#define MAC(H, L, a, b) {                         \
    float p  = __fmul_rn((a), (b));               \
    float pe = __fmaf_rn((a), (b), -p);           \
    float t  = __fadd_rn((H), p);                 \
    float z  = __fsub_rn(t, (H));                 \
    float e  = __fsub_rn(p, z);                   \
    (H) = t;                                      \
    (L) = __fadd_rn((L), __fadd_rn(e, pe));       \
}

// ---------------- scratch (static device memory; no runtime allocation) -------------
__device__ float  g_hhi[NB*CI*HH*WW];        // plain f32 conv output (82 MB)
__device__ float  g_w1tf[CI*9*CI];           // w1 transposed to [ic*9+k][oc]
__device__ unsigned g_k32i[NB*PP], g_k32o[NB*PP], g_vi[NB*PP], g_vo[NB*PP];
__device__ int g_segoff[9]  = {0,90000,180000,270000,360000,450000,540000,630000,720000};
__device__ int g_segoff2[9] = {0,CAND,2*CAND,3*CAND,4*CAND,5*CAND,6*CAND,7*CAND,8*CAND};
__device__ unsigned g_cand[NB*CAND];         // candidate anchor ids per image
__device__ int g_pixflag[NB*10000];
__device__ int g_cnt[NB];
__device__ int g_slotofpix[NB*10000];
__device__ int g_pixofslot[NB*CAND];
__device__ float g_hchi[NB*CAND*CI];         // precise h (hi) per candidate pixel slot
__device__ float g_hclo[NB*CAND*CI];         // precise h (lo)
__device__ double g_cboxd[NB*CAND*4];        // exact f64 boxes per candidate
__device__ ull g_ck[NB*CAND], g_cko[NB*CAND];
__device__ unsigned g_cv[NB*CAND], g_cvo[NB*CAND];
__device__ double g_bsort[NB*PRE*4];
__device__ double g_area[NB*PRE];
__device__ float4 g_bsf[NB*PRE];
__device__ float  g_areaf[NB*PRE];
__device__ int   g_valid[NB*PRE];
__device__ unsigned g_mask[NB*PRE*NW];
__device__ unsigned char g_cubtmp[48u<<20];

// ---------------- anchor base (double math, rounded to f32 = np.float32 array) ------
__device__ __forceinline__ void anchor_ab(int k, float& a0, float& a1, float& a2, float& a3) {
    int ri = k / 3, si = k % 3;
    double r = (ri == 0) ? 0.5 : ((ri == 1) ? 1.0 : 2.0);
    double s = (si == 0) ? 8.0 : ((si == 1) ? 16.0 : 32.0);
    double h = 16.0 * s * sqrt(r);
    double w = 16.0 * s * sqrt(1.0 / r);
    a0 = (float)(8.0 - h / 2.0);
    a1 = (float)(8.0 - w / 2.0);
    a2 = (float)(8.0 + h / 2.0);
    a3 = (float)(8.0 + w / 2.0);
}

// ---------------- weight transpose: [oc][ic][k] -> [ic*9+k][oc] ----------------------
__global__ void wtrans(const float* __restrict__ w1) {
    int idx = blockIdx.x * 256 + threadIdx.x;
    if (idx >= CI * 9 * CI) return;
    int oc = idx % CI;
    int t  = idx / CI;
    int kk = t % 9;
    int ic = t / 9;
    g_w1tf[idx] = w1[(oc * CI + ic) * 9 + kk];
}

// -------- plain-fp32 conv 3x3, pad 1, 256->256, +bias, ReLU, packed FFMA2 -----------
// block: 256 threads; tile: 8 rows x 16 cols x 128 oc; thread: 8 rows x 8 oc (4 pairs)
__global__ __launch_bounds__(256) void conv3f(const float* __restrict__ x,
                                              const float* __restrict__ b1) {
    __shared__ float sx[8][10][18];
    __shared__ float sw[8][9][128];
    int n   = blockIdx.z >> 1;
    int ocb = (blockIdx.z & 1) * 128;
    int bx0 = blockIdx.x * 16;
    int by0 = blockIdx.y * 8;
    int tid = threadIdx.x;
    int c   = tid & 15;
    int g   = tid >> 4;

    ull H[32];
    #pragma unroll
    for (int i = 0; i < 32; i++) H[i] = 0ull;

    for (int icb = 0; icb < CI; icb += 8) {
        for (int idx = tid; idx < 8 * 10 * 18; idx += 256) {
            int ic = idx / 180, rem = idx % 180;
            int r = rem / 18, cc = rem % 18;
            int gy = by0 + r - 1, gx = bx0 + cc - 1;
            float v = 0.f;
            if ((unsigned)gy < 100u && (unsigned)gx < 100u)
                v = x[((n * CI + icb + ic) * HH + gy) * WW + gx];
            sx[ic][r][cc] = v;
        }
        for (int i = tid; i < 2304; i += 256) {
            int ic = i / 288, rem = i % 288;
            int kk = rem / 32, o4 = rem % 32;
            *(float4*)&sw[ic][kk][o4 * 4] =
                *(const float4*)&g_w1tf[((icb + ic) * 9 + kk) * CI + ocb + o4 * 4];
        }
        __syncthreads();

        #pragma unroll 1
        for (int ic = 0; ic < 8; ic++) {
            #pragma unroll
            for (int ky = 0; ky < 3; ky++) {
                #pragma unroll
                for (int kx = 0; kx < 3; kx++) {
                    int k = ky * 3 + kx;
                    ull w0 = *(const ull*)&sw[ic][k][g * 8 + 0];
                    ull w1v = *(const ull*)&sw[ic][k][g * 8 + 2];
                    ull w2 = *(const ull*)&sw[ic][k][g * 8 + 4];
                    ull w3 = *(const ull*)&sw[ic][k][g * 8 + 6];
                    #pragma unroll
                    for (int r = 0; r < 8; r++) {
                        float xv = sx[ic][r + ky][c + kx];
                        ull xx; PACK2(xx, xv, xv);
                        FMA2(H[r * 4 + 0], xx, w0, H[r * 4 + 0]);
                        FMA2(H[r * 4 + 1], xx, w1v, H[r * 4 + 1]);
                        FMA2(H[r * 4 + 2], xx, w2, H[r * 4 + 2]);
                        FMA2(H[r * 4 + 3], xx, w3, H[r * 4 + 3]);
                    }
                }
            }
        }
        __syncthreads();
    }

    int gx = bx0 + c;
    if (gx < WW) {
        #pragma unroll
        for (int r = 0; r < 8; r++) {
            int gy = by0 + r;
            if (gy < HH) {
                #pragma unroll
                for (int p = 0; p < 4; p++) {
                    float h0, h1;
                    unpack2(H[r * 4 + p], h0, h1);
                    int oc = ocb + g * 8 + p * 2;
                    size_t o0 = ((size_t)(n * CI + oc) * HH + gy) * WW + gx;
                    g_hhi[o0] = fmaxf(h0 + b1[oc], 0.f);
                    g_hhi[o0 + (size_t)HH * WW] = fmaxf(h1 + b1[oc + 1], 0.f);
                }
            }
        }
    }
}

// ------- plain-fp32 fused heads: cls/reg outputs + approx score sort keys ------------
__global__ __launch_bounds__(128) void heads_fast(const float* __restrict__ wc,
                                                  const float* __restrict__ bc,
                                                  const float* __restrict__ wr,
                                                  const float* __restrict__ br,
                                                  float* __restrict__ out) {
    __shared__ float sw1[64][54];
    int n = blockIdx.y;
    int p = blockIdx.x * 128 + threadIdx.x;

    ull H[27];
    #pragma unroll
    for (int o = 0; o < 27; o++) H[o] = 0ull;

    for (int icb = 0; icb < CI; icb += 64) {
        for (int idx = threadIdx.x; idx < 64 * 54; idx += 128) {
            int ic = idx / 54, oc = idx % 54;
            sw1[ic][oc] = (oc < 18) ? wc[oc * CI + icb + ic]
                                    : wr[(oc - 18) * CI + icb + ic];
        }
        __syncthreads();
        if (p < HH * WW) {
            #pragma unroll 1
            for (int ic = 0; ic < 64; ic++) {
                float hh = g_hhi[(size_t)(n * CI + icb + ic) * (HH * WW) + p];
                ull hhp; PACK2(hhp, hh, hh);
                #pragma unroll
                for (int q = 0; q < 27; q++) {
                    ull wp = *(const ull*)&sw1[ic][q * 2];
                    FMA2(H[q], hhp, wp, H[q]);
                }
            }
        }
        __syncthreads();
    }
    if (p >= HH * WW) return;

    float hs[54];
    #pragma unroll
    for (int q = 0; q < 27; q++) unpack2(H[q], hs[q * 2], hs[q * 2 + 1]);

    float l[18];
    #pragma unroll
    for (int c18 = 0; c18 < 18; c18++) {
        l[c18] = hs[c18] + bc[c18];
        int k = c18 >> 1, cc = c18 & 1;
        out[OFF_CLS + (n * 2 + cc) * PP + p * KA + k] = l[c18];
    }
    #pragma unroll
    for (int k = 0; k < KA; k++) {
        float s = 1.f / (1.f + __expf(l[2 * k] - l[2 * k + 1]));
        int idx = n * PP + p * KA + k;
        g_k32i[idx] = __float_as_uint(s);
        g_vi[idx] = (unsigned)(p * KA + k);
    }
    #pragma unroll
    for (int c36 = 0; c36 < 36; c36++) {
        int k = c36 >> 2, j = c36 & 3;
        out[OFF_REG + n * (PP * 4) + (p * KA + k) * 4 + j] = hs[18 + c36] + br[c36];
    }
}

// ---------------- clear per-run state (graph replays reuse buffers) ------------------
__global__ void clearw() {
    int idx = blockIdx.x * 256 + threadIdx.x;
    if (idx < NB * 10000) g_pixflag[idx] = 0;
    if (idx < NB) g_cnt[idx] = 0;
}

// ---------------- mark candidate anchors + their pixels ------------------------------
__global__ void mark() {
    int idx = blockIdx.x * 256 + threadIdx.x;
    if (idx >= NB * CAND) return;
    int n = idx / CAND, r = idx - n * CAND;
    unsigned i = g_vo[n * PP + r];
    g_cand[idx] = i;
    g_pixflag[n * 10000 + i / KA] = 1;
}

// ---------------- compact flagged pixels into slots ----------------------------------
__global__ void compact() {
    int idx = blockIdx.x * 256 + threadIdx.x;
    if (idx >= NB * 10000) return;
    if (g_pixflag[idx]) {
        int n = idx / 10000, pix = idx - n * 10000;
        int s = atomicAdd(&g_cnt[n], 1);
        g_slotofpix[idx] = s;
        g_pixofslot[n * CAND + s] = pix;
    }
}

// ------ precise conv recompute for flagged pixels (compensated FFMA2) ---------------
// block: 128 threads (2 oc each), 4 pixel-slots per block
__global__ __launch_bounds__(128) void precise_h(const float* __restrict__ x,
                                                 const float* __restrict__ b1) {
    __shared__ float sxp[4][2304];
    int n = blockIdx.y;
    int s0 = blockIdx.x * 4;
    int cnt = g_cnt[n];
    if (s0 >= cnt) return;
    int tid = threadIdx.x;

    #pragma unroll
    for (int q = 0; q < 4; q++) {
        int sl = s0 + q;
        int pix = g_pixofslot[n * CAND + ((sl < cnt) ? sl : s0)];
        int py = pix / WW, px = pix - py * WW;
        for (int t = tid; t < 2304; t += 128) {
            int ic = t / 9, k = t - ic * 9;
            int ky = k / 3, kx = k - ky * 3;
            int gy = py + ky - 1, gx = px + kx - 1;
            float v = 0.f;
            if ((unsigned)gy < 100u && (unsigned)gx < 100u)
                v = x[((n * CI + ic) * HH + gy) * WW + gx];
            sxp[q][t] = v;
        }
    }
    __syncthreads();

    const float BIAS = 96.0f;
    ull BIASP, NEG1;
    PACK2(BIASP, BIAS, BIAS);
    PACK2(NEG1, -1.0f, -1.0f);
    ull H[4], L[4];
    #pragma unroll
    for (int q = 0; q < 4; q++) { H[q] = BIASP; L[q] = 0ull; }

    const float* wbase = g_w1tf + tid * 2;
    #pragma unroll 4
    for (int t = 0; t < 2304; t++) {
        ull wp = *(const ull*)(wbase + (size_t)t * CI);
        #pragma unroll
        for (int q = 0; q < 4; q++) {
            float xv = sxp[q][t];
            ull xx; PACK2(xx, xv, xv);
            ull Hn, nd, rr;
            FMA2(Hn, xx, wp, H[q]);
            FMA2(nd, Hn, NEG1, H[q]);
            FMA2(rr, xx, wp, nd);
            ADD2(L[q], L[q], rr);
            H[q] = Hn;
        }
    }

    int oc = tid * 2;
    #pragma unroll
    for (int q = 0; q < 4; q++) {
        if (s0 + q < cnt) {
            float h0, h1, l0, l1;
            unpack2(H[q], h0, h1);
            unpack2(L[q], l0, l1);
            size_t base = (size_t)(n * CAND + s0 + q) * CI;
            double v0 = fmax((double)__fsub_rn(h0, BIAS) + (double)l0 + (double)b1[oc], 0.0);
            float vh0 = (float)v0;
            g_hchi[base + oc] = vh0;
            g_hclo[base + oc] = (float)(v0 - (double)vh0);
            double v1 = fmax((double)__fsub_rn(h1, BIAS) + (double)l1 + (double)b1[oc + 1], 0.0);
            float vh1 = (float)v1;
            g_hchi[base + oc + 1] = vh1;
            g_hclo[base + oc + 1] = (float)(v1 - (double)vh1);
        }
    }
}

// ------ exact logits/score/reg + f64 decode for candidates ---------------------------
__global__ void precise_sr(const float* __restrict__ wc,
                           const float* __restrict__ bc,
                           const float* __restrict__ wr,
                           const float* __restrict__ br,
                           const int* __restrict__ pimw,
                           const int* __restrict__ pimh) {
    int idx = blockIdx.x * 256 + threadIdx.x;
    if (idx >= NB * CAND) return;
    int n = idx / CAND, r = idx - n * CAND;
    unsigned i = g_cand[idx];
    int pix = i / KA, k = i - pix * KA;
    int slot = g_slotofpix[n * 10000 + pix];
    size_t base = (size_t)(n * CAND + slot) * CI;

    const float BIAS = 16.0f;
    float Hh[6], Ll[6];
    #pragma unroll
    for (int ch = 0; ch < 6; ch++) { Hh[ch] = BIAS; Ll[ch] = 0.f; }

    for (int ic = 0; ic < CI; ic++) {
        float hh = g_hchi[base + ic];
        float hl = g_hclo[base + ic];
        #pragma unroll
        for (int ch = 0; ch < 6; ch++) {
            float w = (ch < 2) ? wc[(2 * k + ch) * CI + ic]
                               : wr[(4 * k + ch - 2) * CI + ic];
            MAC(Hh[ch], Ll[ch], hh, w);
            Ll[ch] = __fadd_rn(Ll[ch], __fmul_rn(hl, w));
        }
    }

    double l0 = (double)__fsub_rn(Hh[0], BIAS) + (double)Ll[0] + (double)bc[2 * k];
    double l1 = (double)__fsub_rn(Hh[1], BIAS) + (double)Ll[1] + (double)bc[2 * k + 1];
    double score = 1.0 / (1.0 + exp(l0 - l1));
    double dv[4];
    #pragma unroll
    for (int j = 0; j < 4; j++)
        dv[j] = (double)__fsub_rn(Hh[2 + j], BIAS) + (double)Ll[2 + j]
              + (double)br[4 * k + j];

    // f64 decode (anchors replicate numpy f32 arithmetic, then promote)
    int y = pix / WW, x = pix - y * WW;
    float a0, a1, a2, a3;
    anchor_ab(k, a0, a1, a2, a3);
    float sy = (float)(y * 16), sx0 = (float)(x * 16);
    float af0 = sy + a0, af1 = sx0 + a1, af2 = sy + a2, af3 = sx0 + a3;
    float ahf = af2 - af0, awf = af3 - af1;
    float ayf = af0 + 0.5f * ahf, axf = af1 + 0.5f * awf;
    double ah = (double)ahf, aw = (double)awf, ay = (double)ayf, ax = (double)axf;

    double cy = dv[0] * ah + ay, cx = dv[1] * aw + ax;
    double hb = exp(dv[2]) * ah, wb = exp(dv[3]) * aw;

    int wv = pimw[0], hv = pimh[0];
    double imw = (wv > 65536 || wv < 0) ? (double)__int_as_float(wv) : (double)wv;
    double imh = (hv > 65536 || hv < 0) ? (double)__int_as_float(hv) : (double)hv;

    double y1 = fmin(fmax(cy - 0.5 * hb, 0.0), imh);
    double y2 = fmin(fmax(cy + 0.5 * hb, 0.0), imh);
    double x1 = fmin(fmax(cx - 0.5 * wb, 0.0), imw);
    double x2 = fmin(fmax(cx + 0.5 * wb, 0.0), imw);
    bool big = (y2 - y1 >= 16.0) && (x2 - x1 >= 16.0);

    double* bp = &g_cboxd[(size_t)idx * 4];
    bp[0] = y1; bp[1] = x1; bp[2] = y2; bp[3] = x2;
    g_ck[idx] = big ? __double_as_longlong(score) : 0ull;
    g_cv[idx] = (unsigned)r;
}

// ---------------- gather top PRE per batch (from exact candidate sort) ---------------
__global__ void gather_top2() {
    int idx = blockIdx.x * 256 + threadIdx.x;
    if (idx >= NB * PRE) return;
    int n = idx / PRE, rr = idx - n * PRE;
    ull key = g_cko[n * CAND + rr];
    unsigned cs = g_cvo[n * CAND + rr];
    const double* bp = &g_cboxd[((size_t)n * CAND + cs) * 4];
    double y1 = bp[0], x1 = bp[1], y2 = bp[2], x2 = bp[3];
    double* d = &g_bsort[(size_t)idx * 4];
    d[0] = y1; d[1] = x1; d[2] = y2; d[3] = x2;
    double a = (y2 - y1) * (x2 - x1);
    g_area[idx]  = a;
    g_bsf[idx]   = make_float4((float)y1, (float)x1, (float)y2, (float)x2);
    g_areaf[idx] = (float)a;
    g_valid[idx] = (key != 0ull) ? 1 : 0;
}

// ------- NMS mask: f32 IoU with f64 fallback in a guard band around the threshold ----
__global__ __launch_bounds__(96) void nms_mask() {
    int i = blockIdx.x, n = blockIdx.y;
    float4 bi = g_bsf[n * PRE + i];
    float ai = g_areaf[n * PRE + i];
    int lane = threadIdx.x & 31, wp = threadIdx.x >> 5;
    int wstart = i >> 5;
    for (int w = wstart + wp; w < NW; w += 3) {
        int j = w * 32 + lane;
        bool bit = false;
        if (j < PRE && j > i) {
            float4 bj = g_bsf[n * PRE + j];
            float yy1 = fmaxf(bi.x, bj.x);
            float xx1 = fmaxf(bi.y, bj.y);
            float yy2 = fminf(bi.z, bj.z);
            float xx2 = fminf(bi.w, bj.w);
            float inter = fmaxf(yy2 - yy1, 0.f) * fmaxf(xx2 - xx1, 0.f);
            float iou = inter / (ai + g_areaf[n * PRE + j] - inter + 1e-9f);
            if (fabsf(iou - 0.7f) < 1e-4f) {
                const double* di = &g_bsort[((size_t)n * PRE + i) * 4];
                const double* dj = &g_bsort[((size_t)n * PRE + j) * 4];
                double dy1 = fmax(di[0], dj[0]);
                double dx1 = fmax(di[1], dj[1]);
                double dy2 = fmin(di[2], dj[2]);
                double dx2 = fmin(di[3], dj[3]);
                double dint = fmax(dy2 - dy1, 0.0) * fmax(dx2 - dx1, 0.0);
                double diou = dint / (g_area[n * PRE + i] + g_area[n * PRE + j]
                                      - dint + 1e-9);
                bit = diou > 0.7;
            } else {
                bit = iou > 0.7f;
            }
        }
        unsigned m = __ballot_sync(0xffffffffu, bit);
        if (lane == 0) g_mask[((size_t)n * PRE + i) * NW + w] = m;
    }
}

// ---------------- serial greedy scan, 1 warp per batch, write rois + inds ------------
__global__ __launch_bounds__(32) void nms_scan(float* __restrict__ out) {
    int n = blockIdx.x;
    int lane = threadIdx.x;
    unsigned rm0 = 0, rm1 = 0, rm2 = 0;
    int count = 0;
    for (int i = 0; i < PRE && count < POST; i++) {
        int wi = i >> 5;
        int slot = wi >> 5;
        int src  = wi & 31;
        unsigned myw = (slot == 0) ? rm0 : ((slot == 1) ? rm1 : rm2);
        unsigned word = __shfl_sync(0xffffffffu, myw, src);
        bool kept = g_valid[n * PRE + i] && !((word >> (i & 31)) & 1u);
        if (kept) {
            if (lane < 4)
                out[OFF_ROIS + (n * POST + count) * 4 + lane] =
                    (float)g_bsort[((size_t)n * PRE + i) * 4 + lane];
            count++;
            const unsigned* mrow = &g_mask[((size_t)n * PRE + i) * NW];
            int w0 = lane;
            int w1 = lane + 32;
            int w2 = lane + 64;
            if (w0 >= wi && w0 < NW) rm0 |= mrow[w0];
            if (w1 >= wi && w1 < NW) rm1 |= mrow[w1];
            if (w2 >= wi && w2 < NW) rm2 |= mrow[w2];
        }
    }
    for (int m = count; m < POST; m++)
        if (lane < 4) out[OFF_ROIS + (n * POST + m) * 4 + lane] = 0.f;
    for (int m = lane; m < POST; m += 32)
        out[OFF_INDS + n * POST + m] = (float)n;
}

// ---------------- anchors output (f32, replicating numpy f32 arithmetic) -------------
__global__ void anchors_k(float* __restrict__ out) {
    int i = blockIdx.x * 256 + threadIdx.x;
    if (i >= PP) return;
    int cell = i / KA, k = i - cell * KA;
    int y = cell / WW, x = cell - y * WW;
    float a0, a1, a2, a3;
    anchor_ab(k, a0, a1, a2, a3);
    float sy = (float)(y * 16), sx = (float)(x * 16);
    out[OFF_ANCH + i * 4 + 0] = sy + a0;
    out[OFF_ANCH + i * 4 + 1] = sx + a1;
    out[OFF_ANCH + i * 4 + 2] = sy + a2;
    out[OFF_ANCH + i * 4 + 3] = sx + a3;
}

// ---------------- launch -------------------------------------------------------------
extern "C" void kernel_launch(void* const* d_in, const int* in_sizes, int n_in,
                              void* d_out, int out_size) {
    const float* x  = (const float*)d_in[0];
    const float* w1 = (const float*)d_in[1];
    const float* b1 = (const float*)d_in[2];
    const float* wc = (const float*)d_in[3];
    const float* bc = (const float*)d_in[4];
    const float* wr = (const float*)d_in[5];
    const float* br = (const float*)d_in[6];
    const int* imw  = (const int*)d_in[7];
    const int* imh  = (const int*)d_in[8];
    float* out = (float*)d_out;

    wtrans<<<(CI * 9 * CI + 255) / 256, 256>>>(w1);
    conv3f<<<dim3(7, 13, NB * 2), 256>>>(x, b1);
    heads_fast<<<dim3(79, NB), 128>>>(wc, bc, wr, br, out);
    clearw<<<(NB * 10000 + 255) / 256, 256>>>();

    void *pt, *poff, *poff2;
    void *pk32i, *pk32o, *pvi, *pvo, *pck, *pcko, *pcv, *pcvo;
    cudaGetSymbolAddress(&pt, g_cubtmp);
    cudaGetSymbolAddress(&poff, g_segoff);
    cudaGetSymbolAddress(&poff2, g_segoff2);
    cudaGetSymbolAddress(&pk32i, g_k32i);
    cudaGetSymbolAddress(&pk32o, g_k32o);
    cudaGetSymbolAddress(&pvi, g_vi);
    cudaGetSymbolAddress(&pvo, g_vo);
    cudaGetSymbolAddress(&pck, g_ck);
    cudaGetSymbolAddress(&pcko, g_cko);
    cudaGetSymbolAddress(&pcv, g_cv);
    cudaGetSymbolAddress(&pcvo, g_cvo);

    size_t tb = sizeof(g_cubtmp);
    cub::DeviceSegmentedRadixSort::SortPairsDescending(
        pt, tb,
        (const unsigned*)pk32i, (unsigned*)pk32o,
        (const unsigned*)pvi, (unsigned*)pvo,
        NB * PP, NB,
        (const int*)poff, (const int*)poff + 1,
        0, 32, (cudaStream_t)0);

    mark<<<(NB * CAND + 255) / 256, 256>>>();
    compact<<<(NB * 10000 + 255) / 256, 256>>>();
    precise_h<<<dim3(CAND / 4, NB), 128>>>(x, b1);
    precise_sr<<<(NB * CAND + 255) / 256, 256>>>(wc, bc, wr, br, imw, imh);

    size_t tb2 = sizeof(g_cubtmp);
    cub::DeviceSegmentedRadixSort::SortPairsDescending(
        pt, tb2,
        (const ull*)pck, (ull*)pcko,
        (const unsigned*)pcv, (unsigned*)pcvo,
        NB * CAND, NB,
        (const int*)poff2, (const int*)poff2 + 1,
        0, 64, (cudaStream_t)0);

    gather_top2<<<(NB * PRE + 255) / 256, 256>>>();
    nms_mask<<<dim3(PRE, NB), 96>>>();
    nms_scan<<<NB, 32>>>(out);
    anchors_k<<<(PP + 255) / 256, 256>>>(out);
}